// round 7
// baseline (speedup 1.0000x reference)
#include <cuda_runtime.h>
#include <math.h>

#define B_ 32
#define T_ 64
#define N_ 32
#define D_ 128
#define E_ 8
#define K_ 2

// SMEM float offsets (all 16B-aligned bases)
#define OFF_XS   0        // xs_t [128][66]; later o-half(head1) [64][66]
#define OFF_KB   8448     // k_h_t [64][68]; with vb forms o1_t [128][66]
#define OFF_VB   12800    // v_h  [64][68]
#define OFF_AB   17152    // att_t [64][66]
#define OFF_OB0  21376    // o-half(head0) [64][66]
#define SMEM_F   25600    // 102400 bytes

typedef unsigned long long u64;

__device__ int   d_eidx[B_][K_];
__device__ float d_gateg[B_][K_];

// ---- f32x2 packed-math helpers ----
__device__ __forceinline__ u64 f2fma(u64 a, u64 b, u64 c) {
    u64 d; asm("fma.rn.f32x2 %0, %1, %2, %3;" : "=l"(d) : "l"(a), "l"(b), "l"(c)); return d;
}
__device__ __forceinline__ u64 f2mul(u64 a, u64 b) {
    u64 d; asm("mul.rn.f32x2 %0, %1, %2;" : "=l"(d) : "l"(a), "l"(b)); return d;
}
__device__ __forceinline__ u64 fpack(float lo, float hi) {
    u64 d; asm("mov.b64 %0, {%1, %2};" : "=l"(d) : "f"(lo), "f"(hi)); return d;
}
__device__ __forceinline__ u64 fdup(float v) { return fpack(v, v); }
__device__ __forceinline__ float2 funpack(u64 v) {
    float2 r; asm("mov.b64 {%0, %1}, %2;" : "=f"(r.x), "=f"(r.y) : "l"(v)); return r;
}

// ---------------------------------------------------------------------------
// Kernel 1: gating (eval mode)
// ---------------------------------------------------------------------------
__global__ void gate_kernel(const float* __restrict__ x,
                            const float* __restrict__ Wg) {
    const int b   = blockIdx.x;
    const int tid = threadIdx.x;  // 128
    __shared__ float smean[D_];
    __shared__ float slog[E_];

    const float* xb = x + (size_t)b * T_ * N_ * D_;
    float s = 0.f;
    for (int i = 0; i < T_ * N_; ++i) s += xb[(size_t)i * D_ + tid];
    smean[tid] = s * (1.0f / (float)(T_ * N_));
    __syncthreads();

    if (tid < E_) {
        float l = 0.f;
        for (int d = 0; d < D_; ++d) l += smean[d] * Wg[d * E_ + tid];
        slog[tid] = l;
    }
    __syncthreads();

    if (tid == 0) {
        int i0 = 0; float v0 = slog[0];
        for (int e = 1; e < E_; ++e) if (slog[e] > v0) { v0 = slog[e]; i0 = e; }
        int i1 = -1; float v1 = -3.0e38f;
        for (int e = 0; e < E_; ++e) if (e != i0 && slog[e] > v1) { v1 = slog[e]; i1 = e; }
        const float e1  = expf(v1 - v0);
        const float inv = 1.0f / (1.0f + e1);
        d_eidx[b][0]  = i0; d_eidx[b][1]  = i1;
        d_gateg[b][0] = inv; d_gateg[b][1] = e1 * inv;
    }
}

// ---------------------------------------------------------------------------
// Kernel 2: one CTA per (b, n). 512 threads, 2 CTAs/SM (100KB SMEM, <=64 regs).
// Per-expert pipeline, attention processed per head to shrink SMEM.
// ---------------------------------------------------------------------------
__global__ __launch_bounds__(512, 2)
void moe_kernel(const float* __restrict__ x,
                const float* __restrict__ Wd,
                const float* __restrict__ bd,
                const float* __restrict__ Ws,
                const float* __restrict__ bs,
                float* __restrict__ out) {
    extern __shared__ float sm[];
    float* xs  = sm + OFF_XS;   // [d][t] stride 66
    float* kb  = sm + OFF_KB;   // [d_local][kt] stride 68
    float* vb  = sm + OFF_VB;   // [kt][dc_local] stride 68
    float* ab  = sm + OFF_AB;   // att_t [kt][q] stride 66
    float* ob0 = sm + OFF_OB0;  // o dims 0..63 [dc][t] stride 66
    float* o1  = sm + OFF_KB;   // o1_t [128][66] overlays kb+vb

    const int n    = blockIdx.x;
    const int b    = blockIdx.y;
    const int tid  = threadIdx.x;
    const int lane = tid & 31;
    const int wid  = tid >> 5;

    // ---- load x slab coalesced, store transposed xs_t[d][t] (stride 66) ----
    {
        const float4* xg = (const float4*)(x + ((size_t)b * T_ * N_ + n) * D_);
        #pragma unroll
        for (int i = tid; i < T_ * D_ / 4; i += 512) {
            const int t  = i >> 5;
            const int c4 = i & 31;
            float4 v = xg[(size_t)t * (N_ * D_ / 4) + c4];
            const int d0 = c4 * 4;
            xs[(d0 + 0) * 66 + t] = v.x;
            xs[(d0 + 1) * 66 + t] = v.y;
            xs[(d0 + 2) * 66 + t] = v.z;
            xs[(d0 + 3) * 66 + t] = v.w;
        }
    }

    // common mappings
    const int cq4 = (tid & 15) * 4;     // quad index 0..60
    const int tp0 = (tid >> 4) * 2;     // pair row 0..62
    const int c0  = (tid & 63) * 2;     // GEMM2/3 col pair
    const int t0  = (tid >> 6) * 8;     // GEMM2/3 row base (8 rows)

    float accv[2][4][2];
    #pragma unroll
    for (int c = 0; c < 2; ++c)
        #pragma unroll
        for (int p = 0; p < 4; ++p) { accv[c][p][0] = 0.f; accv[c][p][1] = 0.f; }

    __syncthreads();

    for (int slot = 0; slot < K_; ++slot) {
        const int   e = d_eidx[b][slot];
        const float g = d_gateg[b][slot];
        const float* W0 = Wd + ((size_t)(e * 2 + 0) * N_ + n) * D_ * D_;
        const float* W1 = Wd + ((size_t)(e * 2 + 1) * N_ + n) * D_ * D_;
        const float* b0 = bd + ((size_t)(e * 2 + 0) * N_ + n) * D_;
        const float* b1 = bd + ((size_t)(e * 2 + 1) * N_ + n) * D_;

        for (int h = 0; h < 2; ++h) {
            const int hb = h * 64;
            // ---- GEMM1(head): k_h (transposed), v_h ----
            {
                u64 ak[4], av[4];
                const float4 bk = *(const float4*)&b0[hb + cq4];
                const float4 bv = *(const float4*)&b1[hb + cq4];
                ak[0] = fdup(bk.x); ak[1] = fdup(bk.y); ak[2] = fdup(bk.z); ak[3] = fdup(bk.w);
                av[0] = fdup(bv.x); av[1] = fdup(bv.y); av[2] = fdup(bv.z); av[3] = fdup(bv.w);
                #pragma unroll 4
                for (int d = 0; d < D_; ++d) {
                    const u64 xv = *(const u64*)&xs[d * 66 + tp0];
                    const float4 w0 = *(const float4*)&W0[d * D_ + hb + cq4];
                    const float4 w1 = *(const float4*)&W1[d * D_ + hb + cq4];
                    ak[0] = f2fma(xv, fdup(w0.x), ak[0]);
                    ak[1] = f2fma(xv, fdup(w0.y), ak[1]);
                    ak[2] = f2fma(xv, fdup(w0.z), ak[2]);
                    ak[3] = f2fma(xv, fdup(w0.w), ak[3]);
                    av[0] = f2fma(xv, fdup(w1.x), av[0]);
                    av[1] = f2fma(xv, fdup(w1.y), av[1]);
                    av[2] = f2fma(xv, fdup(w1.z), av[2]);
                    av[3] = f2fma(xv, fdup(w1.w), av[3]);
                }
                // k transposed: kb[c][t-pair]
                #pragma unroll
                for (int i = 0; i < 4; ++i)
                    *(u64*)&kb[(cq4 + i) * 68 + tp0] = ak[i];
                // v row-major: vb[t][c-quad]
                const float2 u0 = funpack(av[0]);
                const float2 u1 = funpack(av[1]);
                const float2 u2 = funpack(av[2]);
                const float2 u3 = funpack(av[3]);
                float4 r0; r0.x = u0.x; r0.y = u1.x; r0.z = u2.x; r0.w = u3.x;
                float4 r1; r1.x = u0.y; r1.y = u1.y; r1.z = u2.y; r1.w = u3.y;
                *(float4*)&vb[tp0 * 68 + cq4]       = r0;
                *(float4*)&vb[(tp0 + 1) * 68 + cq4] = r1;
            }
            __syncthreads();

            // ---- att(head): ab[kt][q] = (q.k)/8 ----
            {
                u64 acc[4];
                acc[0] = acc[1] = acc[2] = acc[3] = 0ull;
                #pragma unroll 4
                for (int d = 0; d < 64; ++d) {
                    const float4 kk = *(const float4*)&kb[d * 68 + cq4];
                    const u64 xq = *(const u64*)&xs[(hb + d) * 66 + tp0];
                    acc[0] = f2fma(xq, fdup(kk.x), acc[0]);
                    acc[1] = f2fma(xq, fdup(kk.y), acc[1]);
                    acc[2] = f2fma(xq, fdup(kk.z), acc[2]);
                    acc[3] = f2fma(xq, fdup(kk.w), acc[3]);
                }
                const u64 sc = fdup(0.125f);
                #pragma unroll
                for (int i = 0; i < 4; ++i)
                    *(u64*)&ab[(cq4 + i) * 66 + tp0] = f2mul(acc[i], sc);
            }
            __syncthreads();

            // ---- softmax over kt: warp w handles q = w*4..w*4+3 ----
            {
                const int qb = wid * 4;
                #pragma unroll
                for (int j = 0; j < 4; ++j) {
                    const int q = qb + j;
                    const float a0 = ab[lane * 66 + q];
                    const float a1 = ab[(lane + 32) * 66 + q];
                    float m = fmaxf(a0, a1);
                    #pragma unroll
                    for (int o = 16; o > 0; o >>= 1) m = fmaxf(m, __shfl_xor_sync(0xffffffffu, m, o));
                    const float e0 = __expf(a0 - m);
                    const float e1x = __expf(a1 - m);
                    float s = e0 + e1x;
                    #pragma unroll
                    for (int o = 16; o > 0; o >>= 1) s += __shfl_xor_sync(0xffffffffu, s, o);
                    const float inv = 1.0f / s;
                    ab[lane * 66 + q]        = e0 * inv;
                    ab[(lane + 32) * 66 + q] = e1x * inv;
                }
            }
            __syncthreads();

            // ---- oGEMM(head): o[dc][t] = sum_kt ab[kt][t] * vb[kt][dc] ----
            {
                float* obh = (h == 0) ? ob0 : xs;   // xs dead after att h=1
                u64 acc[4];
                acc[0] = acc[1] = acc[2] = acc[3] = 0ull;
                #pragma unroll 4
                for (int kt = 0; kt < 64; ++kt) {
                    const float4 vv = *(const float4*)&vb[kt * 68 + cq4];
                    const u64 at = *(const u64*)&ab[kt * 66 + tp0];
                    acc[0] = f2fma(at, fdup(vv.x), acc[0]);
                    acc[1] = f2fma(at, fdup(vv.y), acc[1]);
                    acc[2] = f2fma(at, fdup(vv.z), acc[2]);
                    acc[3] = f2fma(at, fdup(vv.w), acc[3]);
                }
                #pragma unroll
                for (int i = 0; i < 4; ++i)
                    *(u64*)&obh[(cq4 + i) * 66 + tp0] = acc[i];
            }
            __syncthreads();
        }

        const float* Wsh0 = Ws + (size_t)(e * 2 + 0) * D_ * D_;
        const float* Wsh1 = Ws + (size_t)(e * 2 + 1) * D_ * D_;
        const float* bsh0 = bs + (e * 2 + 0) * D_;
        const float* bsh1 = bs + (e * 2 + 1) * D_;

        // ---- GEMM2: o1 = relu(o @ Ws0 + bs0) -> o1 (overlays kb/vb) ----
        {
            u64 a2[2][4];
            const float2 bb = *(const float2*)&bsh0[c0];
            #pragma unroll
            for (int p = 0; p < 4; ++p) { a2[0][p] = fdup(bb.x); a2[1][p] = fdup(bb.y); }
            #pragma unroll 2
            for (int d = 0; d < 64; ++d) {
                const float2 w = *(const float2*)&Wsh0[d * D_ + c0];
                const u64 wx = fdup(w.x), wy = fdup(w.y);
                #pragma unroll
                for (int p = 0; p < 4; ++p) {
                    const u64 ov = *(const u64*)&ob0[d * 66 + t0 + 2 * p];
                    a2[0][p] = f2fma(ov, wx, a2[0][p]);
                    a2[1][p] = f2fma(ov, wy, a2[1][p]);
                }
            }
            #pragma unroll 2
            for (int d = 64; d < 128; ++d) {
                const float2 w = *(const float2*)&Wsh0[d * D_ + c0];
                const u64 wx = fdup(w.x), wy = fdup(w.y);
                #pragma unroll
                for (int p = 0; p < 4; ++p) {
                    const u64 ov = *(const u64*)&xs[(d - 64) * 66 + t0 + 2 * p];
                    a2[0][p] = f2fma(ov, wx, a2[0][p]);
                    a2[1][p] = f2fma(ov, wy, a2[1][p]);
                }
            }
            #pragma unroll
            for (int p = 0; p < 4; ++p) {
                const float2 u0 = funpack(a2[0][p]);
                const float2 u1 = funpack(a2[1][p]);
                *(u64*)&o1[(c0 + 0) * 66 + t0 + 2 * p] = fpack(fmaxf(u0.x, 0.f), fmaxf(u0.y, 0.f));
                *(u64*)&o1[(c0 + 1) * 66 + t0 + 2 * p] = fpack(fmaxf(u1.x, 0.f), fmaxf(u1.y, 0.f));
            }
        }
        __syncthreads();

        // ---- GEMM3: out_e = o1 @ Ws1 + bs1 ; accv += g * exp ----
        {
            u64 a3[2][4];
            const float2 bb = *(const float2*)&bsh1[c0];
            #pragma unroll
            for (int p = 0; p < 4; ++p) { a3[0][p] = fdup(bb.x); a3[1][p] = fdup(bb.y); }
            #pragma unroll 2
            for (int d = 0; d < D_; ++d) {
                const float2 w = *(const float2*)&Wsh1[d * D_ + c0];
                const u64 wx = fdup(w.x), wy = fdup(w.y);
                #pragma unroll
                for (int p = 0; p < 4; ++p) {
                    const u64 ov = *(const u64*)&o1[d * 66 + t0 + 2 * p];
                    a3[0][p] = f2fma(ov, wx, a3[0][p]);
                    a3[1][p] = f2fma(ov, wy, a3[1][p]);
                }
            }
            #pragma unroll
            for (int p = 0; p < 4; ++p) {
                const float2 u0 = funpack(a3[0][p]);
                const float2 u1 = funpack(a3[1][p]);
                accv[0][p][0] += g * __expf(u0.x);
                accv[0][p][1] += g * __expf(u0.y);
                accv[1][p][0] += g * __expf(u1.x);
                accv[1][p][1] += g * __expf(u1.y);
            }
        }
        __syncthreads();   // before next expert overwrites kb/vb/xs(o-half)
        if (slot == 0) {
            // restore xs from global for expert 2 (o head1 clobbered it)
            const float4* xg = (const float4*)(x + ((size_t)b * T_ * N_ + n) * D_);
            #pragma unroll
            for (int i = tid; i < T_ * D_ / 4; i += 512) {
                const int t  = i >> 5;
                const int c4 = i & 31;
                float4 v = xg[(size_t)t * (N_ * D_ / 4) + c4];
                const int d0 = c4 * 4;
                xs[(d0 + 0) * 66 + t] = v.x;
                xs[(d0 + 1) * 66 + t] = v.y;
                xs[(d0 + 2) * 66 + t] = v.z;
                xs[(d0 + 3) * 66 + t] = v.w;
            }
            __syncthreads();
        }
    }

    // ---- combine epilogue ----
    const float EPSF = 2.2204460492503131e-16f;
    #pragma unroll
    for (int p = 0; p < 4; ++p) {
        #pragma unroll
        for (int r = 0; r < 2; ++r) {
            const int t = t0 + 2 * p + r;
            float v0 = accv[0][p][r]; if (v0 == 0.f) v0 = EPSF;
            float v1 = accv[1][p][r]; if (v1 == 0.f) v1 = EPSF;
            *(u64*)&out[(((size_t)b * T_ + t) * N_ + n) * D_ + c0] =
                fpack(__logf(v0), __logf(v1));
        }
    }
}

// ---------------------------------------------------------------------------
// launcher
// ---------------------------------------------------------------------------
extern "C" void kernel_launch(void* const* d_in, const int* in_sizes, int n_in,
                              void* d_out, int out_size) {
    const float* x  = (const float*)d_in[0];
    const float* Wg = (const float*)d_in[1];
    const float* Wd = (const float*)d_in[2];
    const float* bd = (const float*)d_in[3];
    const float* Ws = (const float*)d_in[4];
    const float* bs = (const float*)d_in[5];
    float* out = (float*)d_out;

    const int smem_bytes = SMEM_F * (int)sizeof(float); // 102400 B
    cudaFuncSetAttribute(moe_kernel, cudaFuncAttributeMaxDynamicSharedMemorySize, smem_bytes);

    gate_kernel<<<B_, 128>>>(x, Wg);
    dim3 grid(N_, B_);
    moe_kernel<<<grid, 512, smem_bytes>>>(x, Wd, bd, Ws, bs, out);
}

// round 8
// speedup vs baseline: 3.1544x; 3.1544x over previous
#include <cuda_runtime.h>
#include <math.h>

#define B_ 32
#define T_ 64
#define N_ 32
#define D_ 128
#define E_ 8
#define K_ 2

typedef unsigned long long u64;
typedef unsigned int u32;

// SMEM float offsets
#define OFF_XS 0        // x      [64][132] (A-role, stride 132)
#define OFF_KS 8448     // K      [64][132] (att B, n-major -> 132); O1 NOT here
#define OFF_VS 16896    // V      [64][136] (PV B, k-major -> 136)
#define OFF_S  25600    // S/P    [2][64][68] (A-role 68); later O1 [64][132]
#define OFF_O  34304    // O      [64][132] (A-role)
#define OFF_WS 42752    // Wslabs [2][32][136] (B, k-major -> 136)
#define SMEM_F 51456    // 205824 bytes

__device__ int   d_eidx[B_][K_];
__device__ float d_gateg[B_][K_];

__device__ __forceinline__ u32 cvt_tf32(float x) {
    u32 u; asm("cvt.rna.tf32.f32 %0, %1;" : "=r"(u) : "f"(x)); return u;
}
__device__ __forceinline__ float tf32f(float x) { return __uint_as_float(cvt_tf32(x)); }
__device__ __forceinline__ u64 fpack(float lo, float hi) {
    u64 d; asm("mov.b64 %0, {%1, %2};" : "=l"(d) : "f"(lo), "f"(hi)); return d;
}
__device__ __forceinline__ void mma_tf32(float* c, const u32* a, const u32* b) {
    asm volatile(
        "mma.sync.aligned.m16n8k8.row.col.f32.tf32.tf32.f32 "
        "{%0,%1,%2,%3}, {%4,%5,%6,%7}, {%8,%9}, {%0,%1,%2,%3};\n"
        : "+f"(c[0]), "+f"(c[1]), "+f"(c[2]), "+f"(c[3])
        : "r"(a[0]), "r"(a[1]), "r"(a[2]), "r"(a[3]), "r"(b[0]), "r"(b[1]));
}

// ---------------------------------------------------------------------------
// Kernel 1: gating (eval mode)
// ---------------------------------------------------------------------------
__global__ void gate_kernel(const float* __restrict__ x,
                            const float* __restrict__ Wg) {
    const int b   = blockIdx.x;
    const int tid = threadIdx.x;  // 128
    __shared__ float smean[D_];
    __shared__ float slog[E_];

    const float* xb = x + (size_t)b * T_ * N_ * D_;
    float s = 0.f;
    for (int i = 0; i < T_ * N_; ++i) s += xb[(size_t)i * D_ + tid];
    smean[tid] = s * (1.0f / (float)(T_ * N_));
    __syncthreads();

    if (tid < E_) {
        float l = 0.f;
        for (int d = 0; d < D_; ++d) l += smean[d] * Wg[d * E_ + tid];
        slog[tid] = l;
    }
    __syncthreads();

    if (tid == 0) {
        int i0 = 0; float v0 = slog[0];
        for (int e = 1; e < E_; ++e) if (slog[e] > v0) { v0 = slog[e]; i0 = e; }
        int i1 = -1; float v1 = -3.0e38f;
        for (int e = 0; e < E_; ++e) if (e != i0 && slog[e] > v1) { v1 = slog[e]; i1 = e; }
        const float e1  = expf(v1 - v0);
        const float inv = 1.0f / (1.0f + e1);
        d_eidx[b][0]  = i0; d_eidx[b][1]  = i1;
        d_gateg[b][0] = inv; d_gateg[b][1] = e1 * inv;
    }
}

// ---------------------------------------------------------------------------
// Kernel 2: one CTA per (b,n). 512 threads / 16 warps. All GEMMs on tensor
// pipe via mma.sync m16n8k8 tf32 with manual (conflict-free) fragment loads.
// ---------------------------------------------------------------------------
__global__ __launch_bounds__(512, 1)
void moe_kernel(const float* __restrict__ x,
                const float* __restrict__ Wd,
                const float* __restrict__ bd,
                const float* __restrict__ Ws,
                const float* __restrict__ bs,
                float* __restrict__ out) {
    extern __shared__ float sm[];
    float* XS = sm + OFF_XS;
    float* KS = sm + OFF_KS;
    float* VS = sm + OFF_VS;
    float* S  = sm + OFF_S;
    float* O  = sm + OFF_O;
    float* WS = sm + OFF_WS;

    const int n    = blockIdx.x;
    const int b    = blockIdx.y;
    const int tid  = threadIdx.x;
    const int lane = tid & 31;
    const int wid  = tid >> 5;
    const int g    = lane >> 2;   // fragment group (0..7)
    const int tq   = lane & 3;    // fragment thread-in-group (0..3)

    // ---- load x [T][D] -> XS row-major, tf32-rounded ----
    {
        const float4* xg = (const float4*)(x + ((size_t)b * T_ * N_ + n) * D_);
        #pragma unroll
        for (int i = tid; i < T_ * D_ / 4; i += 512) {
            const int t  = i >> 5;
            const int c4 = (i & 31) * 4;
            float4 v = xg[(size_t)t * (N_ * D_ / 4) + (c4 >> 2)];
            float* dst = XS + t * 132 + c4;
            dst[0] = tf32f(v.x); dst[1] = tf32f(v.y);
            dst[2] = tf32f(v.z); dst[3] = tf32f(v.w);
        }
    }

    // GEMM1 mapping: 16 warps = 2 matrices x (2 row-tiles of 32) x (4 col-tiles of 32)
    const int matId = wid >> 3;
    const int g1_m0 = (wid & 1) * 32;
    const int g1_n0 = ((wid >> 1) & 3) * 32;
    // att/PV mapping: 16 warps = 2 heads x (4 m-tiles of 16) x (2 n-tiles of 32)
    const int h     = wid >> 3;
    const int a_m0  = (wid & 3) * 16;
    const int a_n0  = ((wid >> 2) & 1) * 32;
    const int hb    = h * 64;
    // GEMM2/3 mapping: (4 m-tiles of 16) x (4 n-tiles of 32)
    const int g2_m0 = (wid & 3) * 16;
    const int g2_n0 = (wid >> 2) * 32;

    float accv[4][4];
    #pragma unroll
    for (int ni = 0; ni < 4; ++ni)
        #pragma unroll
        for (int c = 0; c < 4; ++c) accv[ni][c] = 0.f;

    for (int slot = 0; slot < K_; ++slot) {
        const int   e  = d_eidx[b][slot];
        const float gg = d_gateg[b][slot];

        // =================== GEMM1: K = x@W0+b0, V = x@W1+b1 ===================
        {
            const float* W0g = Wd + ((size_t)(e * 2 + 0) * N_ + n) * (D_ * D_);
            const float* W1g = Wd + ((size_t)(e * 2 + 1) * N_ + n) * (D_ * D_);
            const float* bm  = bd + ((size_t)(e * 2 + matId) * N_ + n) * D_;

            float acc[2][4][4];
            #pragma unroll
            for (int ni = 0; ni < 4; ++ni) {
                const float b0v = bm[g1_n0 + 8 * ni + 2 * tq];
                const float b1v = bm[g1_n0 + 8 * ni + 2 * tq + 1];
                #pragma unroll
                for (int mi = 0; mi < 2; ++mi) {
                    acc[mi][ni][0] = b0v; acc[mi][ni][1] = b1v;
                    acc[mi][ni][2] = b0v; acc[mi][ni][3] = b1v;
                }
            }
            for (int s = 0; s < 4; ++s) {
                __syncthreads();
                #pragma unroll
                for (int j = tid; j < 2048; j += 512) {
                    const int mat = j >> 10;
                    const int r   = (j >> 5) & 31;
                    const int c4  = (j & 31) * 4;
                    const float4 w = *(const float4*)((mat ? W1g : W0g) + (s * 32 + r) * D_ + c4);
                    float* dst = WS + mat * 4352 + r * 136 + c4;
                    dst[0] = tf32f(w.x); dst[1] = tf32f(w.y);
                    dst[2] = tf32f(w.z); dst[3] = tf32f(w.w);
                }
                __syncthreads();
                #pragma unroll
                for (int kk = 0; kk < 4; ++kk) {
                    const int kg = s * 32 + kk * 8;
                    u32 a[2][4];
                    #pragma unroll
                    for (int mi = 0; mi < 2; ++mi) {
                        const int r = g1_m0 + 16 * mi;
                        a[mi][0] = __float_as_uint(XS[(r + g)     * 132 + kg + tq]);
                        a[mi][1] = __float_as_uint(XS[(r + 8 + g) * 132 + kg + tq]);
                        a[mi][2] = __float_as_uint(XS[(r + g)     * 132 + kg + tq + 4]);
                        a[mi][3] = __float_as_uint(XS[(r + 8 + g) * 132 + kg + tq + 4]);
                    }
                    const float* wsb = WS + matId * 4352 + (kk * 8) * 136;
                    u32 bf[4][2];
                    #pragma unroll
                    for (int ni = 0; ni < 4; ++ni) {
                        bf[ni][0] = __float_as_uint(wsb[tq       * 136 + g1_n0 + 8 * ni + g]);
                        bf[ni][1] = __float_as_uint(wsb[(tq + 4) * 136 + g1_n0 + 8 * ni + g]);
                    }
                    #pragma unroll
                    for (int mi = 0; mi < 2; ++mi)
                        #pragma unroll
                        for (int ni = 0; ni < 4; ++ni)
                            mma_tf32(acc[mi][ni], a[mi], bf[ni]);
                }
            }
            // store K (stride 132) / V (stride 136), tf32-rounded
            float* dst = matId ? VS : KS;
            const int ds = matId ? 136 : 132;
            #pragma unroll
            for (int mi = 0; mi < 2; ++mi)
                #pragma unroll
                for (int ni = 0; ni < 4; ++ni) {
                    const int r  = g1_m0 + 16 * mi;
                    const int cc = g1_n0 + 8 * ni + 2 * tq;
                    *(u64*)&dst[(r + g)     * ds + cc] = fpack(tf32f(acc[mi][ni][0]), tf32f(acc[mi][ni][1]));
                    *(u64*)&dst[(r + 8 + g) * ds + cc] = fpack(tf32f(acc[mi][ni][2]), tf32f(acc[mi][ni][3]));
                }
            __syncthreads();
        }

        // =================== att: S = Q K^T / 8 (per head) ===================
        {
            float sa[4][4];
            #pragma unroll
            for (int ni = 0; ni < 4; ++ni)
                #pragma unroll
                for (int c = 0; c < 4; ++c) sa[ni][c] = 0.f;
            #pragma unroll
            for (int ks = 0; ks < 8; ++ks) {
                const int k = ks * 8;
                u32 a[4];
                a[0] = __float_as_uint(XS[(a_m0 + g)     * 132 + hb + k + tq]);
                a[1] = __float_as_uint(XS[(a_m0 + 8 + g) * 132 + hb + k + tq]);
                a[2] = __float_as_uint(XS[(a_m0 + g)     * 132 + hb + k + tq + 4]);
                a[3] = __float_as_uint(XS[(a_m0 + 8 + g) * 132 + hb + k + tq + 4]);
                u32 bf[4][2];
                #pragma unroll
                for (int ni = 0; ni < 4; ++ni) {
                    bf[ni][0] = __float_as_uint(KS[(a_n0 + 8 * ni + g) * 132 + hb + k + tq]);
                    bf[ni][1] = __float_as_uint(KS[(a_n0 + 8 * ni + g) * 132 + hb + k + tq + 4]);
                }
                #pragma unroll
                for (int ni = 0; ni < 4; ++ni) mma_tf32(sa[ni], a, bf[ni]);
            }
            float* Sh = S + h * 4352;
            #pragma unroll
            for (int ni = 0; ni < 4; ++ni) {
                const int cc = a_n0 + 8 * ni + 2 * tq;
                *(u64*)&Sh[(a_m0 + g)     * 68 + cc] = fpack(0.125f * sa[ni][0], 0.125f * sa[ni][1]);
                *(u64*)&Sh[(a_m0 + 8 + g) * 68 + cc] = fpack(0.125f * sa[ni][2], 0.125f * sa[ni][3]);
            }
            __syncthreads();
        }

        // =================== softmax over kt (rows contiguous) ===================
        {
            #pragma unroll
            for (int j = 0; j < 8; ++j) {
                const int r = wid * 8 + j;
                float* row = S + (r >> 6) * 4352 + (r & 63) * 68;
                const float a0 = row[lane];
                const float a1 = row[lane + 32];
                float m = fmaxf(a0, a1);
                #pragma unroll
                for (int o = 16; o > 0; o >>= 1) m = fmaxf(m, __shfl_xor_sync(0xffffffffu, m, o));
                const float e0 = __expf(a0 - m);
                const float e1 = __expf(a1 - m);
                float sum = e0 + e1;
                #pragma unroll
                for (int o = 16; o > 0; o >>= 1) sum += __shfl_xor_sync(0xffffffffu, sum, o);
                const float inv = 1.0f / sum;
                row[lane]      = tf32f(e0 * inv);
                row[lane + 32] = tf32f(e1 * inv);
            }
            __syncthreads();
        }

        // =================== O = P V (per head) ===================
        {
            float oa[4][4];
            #pragma unroll
            for (int ni = 0; ni < 4; ++ni)
                #pragma unroll
                for (int c = 0; c < 4; ++c) oa[ni][c] = 0.f;
            const float* Ph = S + h * 4352;
            #pragma unroll
            for (int ks = 0; ks < 8; ++ks) {
                const int k = ks * 8;
                u32 a[4];
                a[0] = __float_as_uint(Ph[(a_m0 + g)     * 68 + k + tq]);
                a[1] = __float_as_uint(Ph[(a_m0 + 8 + g) * 68 + k + tq]);
                a[2] = __float_as_uint(Ph[(a_m0 + g)     * 68 + k + tq + 4]);
                a[3] = __float_as_uint(Ph[(a_m0 + 8 + g) * 68 + k + tq + 4]);
                u32 bf[4][2];
                #pragma unroll
                for (int ni = 0; ni < 4; ++ni) {
                    bf[ni][0] = __float_as_uint(VS[(k + tq)     * 136 + hb + a_n0 + 8 * ni + g]);
                    bf[ni][1] = __float_as_uint(VS[(k + tq + 4) * 136 + hb + a_n0 + 8 * ni + g]);
                }
                #pragma unroll
                for (int ni = 0; ni < 4; ++ni) mma_tf32(oa[ni], a, bf[ni]);
            }
            #pragma unroll
            for (int ni = 0; ni < 4; ++ni) {
                const int cc = hb + a_n0 + 8 * ni + 2 * tq;
                *(u64*)&O[(a_m0 + g)     * 132 + cc] = fpack(tf32f(oa[ni][0]), tf32f(oa[ni][1]));
                *(u64*)&O[(a_m0 + 8 + g) * 132 + cc] = fpack(tf32f(oa[ni][2]), tf32f(oa[ni][3]));
            }
            __syncthreads();
        }

        // =================== GEMM2: O1 = relu(O @ Ws0 + bs0) ===================
        {
            const float* Wg2 = Ws + (size_t)(e * 2 + 0) * D_ * D_;
            const float* bsp = bs + (e * 2 + 0) * D_;
            float acc[4][4];
            #pragma unroll
            for (int ni = 0; ni < 4; ++ni) {
                const float b0v = bsp[g2_n0 + 8 * ni + 2 * tq];
                const float b1v = bsp[g2_n0 + 8 * ni + 2 * tq + 1];
                acc[ni][0] = b0v; acc[ni][1] = b1v; acc[ni][2] = b0v; acc[ni][3] = b1v;
            }
            for (int s = 0; s < 4; ++s) {
                __syncthreads();
                #pragma unroll
                for (int j = tid; j < 1024; j += 512) {
                    const int r  = j >> 5;
                    const int c4 = (j & 31) * 4;
                    const float4 w = *(const float4*)(Wg2 + (s * 32 + r) * D_ + c4);
                    float* dst = WS + r * 136 + c4;
                    dst[0] = tf32f(w.x); dst[1] = tf32f(w.y);
                    dst[2] = tf32f(w.z); dst[3] = tf32f(w.w);
                }
                __syncthreads();
                #pragma unroll
                for (int kk = 0; kk < 4; ++kk) {
                    const int kg = s * 32 + kk * 8;
                    u32 a[4];
                    a[0] = __float_as_uint(O[(g2_m0 + g)     * 132 + kg + tq]);
                    a[1] = __float_as_uint(O[(g2_m0 + 8 + g) * 132 + kg + tq]);
                    a[2] = __float_as_uint(O[(g2_m0 + g)     * 132 + kg + tq + 4]);
                    a[3] = __float_as_uint(O[(g2_m0 + 8 + g) * 132 + kg + tq + 4]);
                    const float* wsb = WS + (kk * 8) * 136;
                    u32 bf[4][2];
                    #pragma unroll
                    for (int ni = 0; ni < 4; ++ni) {
                        bf[ni][0] = __float_as_uint(wsb[tq       * 136 + g2_n0 + 8 * ni + g]);
                        bf[ni][1] = __float_as_uint(wsb[(tq + 4) * 136 + g2_n0 + 8 * ni + g]);
                    }
                    #pragma unroll
                    for (int ni = 0; ni < 4; ++ni) mma_tf32(acc[ni], a, bf[ni]);
                }
            }
            // O1 -> S region, flat stride 132 (relu + tf32)
            float* O1 = S;
            #pragma unroll
            for (int ni = 0; ni < 4; ++ni) {
                const int cc = g2_n0 + 8 * ni + 2 * tq;
                *(u64*)&O1[(g2_m0 + g)     * 132 + cc] =
                    fpack(tf32f(fmaxf(acc[ni][0], 0.f)), tf32f(fmaxf(acc[ni][1], 0.f)));
                *(u64*)&O1[(g2_m0 + 8 + g) * 132 + cc] =
                    fpack(tf32f(fmaxf(acc[ni][2], 0.f)), tf32f(fmaxf(acc[ni][3], 0.f)));
            }
        }

        // =================== GEMM3: out_e = O1 @ Ws1 + bs1 ; accv += g*exp ===================
        {
            const float* Wg3 = Ws + (size_t)(e * 2 + 1) * D_ * D_;
            const float* bsp = bs + (e * 2 + 1) * D_;
            const float* O1 = S;
            float acc[4][4];
            #pragma unroll
            for (int ni = 0; ni < 4; ++ni) {
                const float b0v = bsp[g2_n0 + 8 * ni + 2 * tq];
                const float b1v = bsp[g2_n0 + 8 * ni + 2 * tq + 1];
                acc[ni][0] = b0v; acc[ni][1] = b1v; acc[ni][2] = b0v; acc[ni][3] = b1v;
            }
            for (int s = 0; s < 4; ++s) {
                __syncthreads();   // also orders O1 stores before first stage's mma
                #pragma unroll
                for (int j = tid; j < 1024; j += 512) {
                    const int r  = j >> 5;
                    const int c4 = (j & 31) * 4;
                    const float4 w = *(const float4*)(Wg3 + (s * 32 + r) * D_ + c4);
                    float* dst = WS + r * 136 + c4;
                    dst[0] = tf32f(w.x); dst[1] = tf32f(w.y);
                    dst[2] = tf32f(w.z); dst[3] = tf32f(w.w);
                }
                __syncthreads();
                #pragma unroll
                for (int kk = 0; kk < 4; ++kk) {
                    const int kg = s * 32 + kk * 8;
                    u32 a[4];
                    a[0] = __float_as_uint(O1[(g2_m0 + g)     * 132 + kg + tq]);
                    a[1] = __float_as_uint(O1[(g2_m0 + 8 + g) * 132 + kg + tq]);
                    a[2] = __float_as_uint(O1[(g2_m0 + g)     * 132 + kg + tq + 4]);
                    a[3] = __float_as_uint(O1[(g2_m0 + 8 + g) * 132 + kg + tq + 4]);
                    const float* wsb = WS + (kk * 8) * 136;
                    u32 bf[4][2];
                    #pragma unroll
                    for (int ni = 0; ni < 4; ++ni) {
                        bf[ni][0] = __float_as_uint(wsb[tq       * 136 + g2_n0 + 8 * ni + g]);
                        bf[ni][1] = __float_as_uint(wsb[(tq + 4) * 136 + g2_n0 + 8 * ni + g]);
                    }
                    #pragma unroll
                    for (int ni = 0; ni < 4; ++ni) mma_tf32(acc[ni], a, bf[ni]);
                }
            }
            #pragma unroll
            for (int ni = 0; ni < 4; ++ni)
                #pragma unroll
                for (int c = 0; c < 4; ++c)
                    accv[ni][c] += gg * __expf(acc[ni][c]);
            __syncthreads();   // before next expert's GEMM1 staging/stores
        }
    }

    // ---- combine epilogue ----
    const float EPSF = 2.2204460492503131e-16f;
    #pragma unroll
    for (int ni = 0; ni < 4; ++ni) {
        const int cc = g2_n0 + 8 * ni + 2 * tq;
        const int t0r = g2_m0 + g;
        const int t1r = g2_m0 + 8 + g;
        float v0 = accv[ni][0]; if (v0 == 0.f) v0 = EPSF;
        float v1 = accv[ni][1]; if (v1 == 0.f) v1 = EPSF;
        float v2 = accv[ni][2]; if (v2 == 0.f) v2 = EPSF;
        float v3 = accv[ni][3]; if (v3 == 0.f) v3 = EPSF;
        *(u64*)&out[(((size_t)b * T_ + t0r) * N_ + n) * D_ + cc] = fpack(__logf(v0), __logf(v1));
        *(u64*)&out[(((size_t)b * T_ + t1r) * N_ + n) * D_ + cc] = fpack(__logf(v2), __logf(v3));
    }
}

// ---------------------------------------------------------------------------
// launcher
// ---------------------------------------------------------------------------
extern "C" void kernel_launch(void* const* d_in, const int* in_sizes, int n_in,
                              void* d_out, int out_size) {
    const float* x  = (const float*)d_in[0];
    const float* Wg = (const float*)d_in[1];
    const float* Wd = (const float*)d_in[2];
    const float* bd = (const float*)d_in[3];
    const float* Ws = (const float*)d_in[4];
    const float* bs = (const float*)d_in[5];
    float* out = (float*)d_out;

    const int smem_bytes = SMEM_F * (int)sizeof(float); // 205824 B
    cudaFuncSetAttribute(moe_kernel, cudaFuncAttributeMaxDynamicSharedMemorySize, smem_bytes);

    gate_kernel<<<B_, 128>>>(x, Wg);
    dim3 grid(N_, B_);
    moe_kernel<<<grid, 512, smem_bytes>>>(x, Wd, bd, Ws, bs, out);
}

// round 9
// speedup vs baseline: 3.9719x; 1.2592x over previous
#include <cuda_runtime.h>
#include <cuda_fp16.h>
#include <math.h>

#define B_ 32
#define T_ 64
#define N_ 32
#define D_ 128
#define E_ 8
#define K_ 2

typedef unsigned long long u64;
typedef unsigned int u32;

// SMEM u32-unit offsets (half2 buffers are u32 arrays; S is fp32)
#define OFF_XA  0        // x     [64][68]  half2 (d-pairs)
#define OFF_KS  4352     // K     [64][68]  half2 (dc-pairs)
#define OFF_VT  8704     // V^T   [128][36] half2 (t-pairs)
#define OFF_PS  13312    // P     [2][64][36] half2 (kt-pairs)
#define OFF_OS  17920    // O     [64][68]  half2
#define OFF_O1  22272    // O1    [64][68]  half2
#define OFF_WS  26624    // Wslab [2][128][20] half2 (d-pairs, transposed)
#define OFF_S   31744    // S     [2][64][68] fp32
#define SMEM_U  40448    // *4 = 161792 bytes

__device__ int   d_eidx[B_][K_];
__device__ float d_gateg[B_][K_];

__device__ __forceinline__ u64 fpack(float lo, float hi) {
    u64 d; asm("mov.b64 %0, {%1, %2};" : "=l"(d) : "f"(lo), "f"(hi)); return d;
}
__device__ __forceinline__ u32 h2pack(float lo, float hi) {
    __half2 h = __floats2half2_rn(lo, hi);
    return *(u32*)&h;
}
__device__ __forceinline__ void mma_f16(float* c, const u32* a, const u32* b) {
    asm volatile(
        "mma.sync.aligned.m16n8k16.row.col.f32.f16.f16.f32 "
        "{%0,%1,%2,%3}, {%4,%5,%6,%7}, {%8,%9}, {%0,%1,%2,%3};\n"
        : "+f"(c[0]), "+f"(c[1]), "+f"(c[2]), "+f"(c[3])
        : "r"(a[0]), "r"(a[1]), "r"(a[2]), "r"(a[3]), "r"(b[0]), "r"(b[1]));
}

// ---------------------------------------------------------------------------
// Kernel 1: gating (eval mode)
// ---------------------------------------------------------------------------
__global__ void gate_kernel(const float* __restrict__ x,
                            const float* __restrict__ Wg) {
    const int b   = blockIdx.x;
    const int tid = threadIdx.x;  // 128
    __shared__ float smean[D_];
    __shared__ float slog[E_];

    const float* xb = x + (size_t)b * T_ * N_ * D_;
    float s = 0.f;
    for (int i = 0; i < T_ * N_; ++i) s += xb[(size_t)i * D_ + tid];
    smean[tid] = s * (1.0f / (float)(T_ * N_));
    __syncthreads();

    if (tid < E_) {
        float l = 0.f;
        for (int d = 0; d < D_; ++d) l += smean[d] * Wg[d * E_ + tid];
        slog[tid] = l;
    }
    __syncthreads();

    if (tid == 0) {
        int i0 = 0; float v0 = slog[0];
        for (int e = 1; e < E_; ++e) if (slog[e] > v0) { v0 = slog[e]; i0 = e; }
        int i1 = -1; float v1 = -3.0e38f;
        for (int e = 0; e < E_; ++e) if (e != i0 && slog[e] > v1) { v1 = slog[e]; i1 = e; }
        const float e1  = expf(v1 - v0);
        const float inv = 1.0f / (1.0f + e1);
        d_eidx[b][0]  = i0; d_eidx[b][1]  = i1;
        d_gateg[b][0] = inv; d_gateg[b][1] = e1 * inv;
    }
}

// ---------------------------------------------------------------------------
// Kernel 2: one CTA per (b,n). 512 threads / 16 warps. All GEMMs via fp16
// mma.sync m16n8k16 (fp32 accum). half2-packed fragments = 1 LDS.32 each.
// ---------------------------------------------------------------------------
__global__ __launch_bounds__(512, 1)
void moe_kernel(const float* __restrict__ x,
                const float* __restrict__ Wd,
                const float* __restrict__ bd,
                const float* __restrict__ Ws,
                const float* __restrict__ bs,
                float* __restrict__ out) {
    extern __shared__ u32 smu[];
    u32*   XA = smu + OFF_XA;
    u32*   KS = smu + OFF_KS;
    u32*   VT = smu + OFF_VT;
    u32*   PS = smu + OFF_PS;
    u32*   OS = smu + OFF_OS;
    u32*   O1 = smu + OFF_O1;
    u32*   WS = smu + OFF_WS;
    float* S  = (float*)(smu + OFF_S);

    const int n    = blockIdx.x;
    const int b    = blockIdx.y;
    const int tid  = threadIdx.x;
    const int lane = tid & 31;
    const int wid  = tid >> 5;
    const int g    = lane >> 2;   // fragment group row (0..7)
    const int tq   = lane & 3;    // fragment thread-in-group (0..3)

    // ---- load x [T][D] -> XA [t][d2] half2 ----
    {
        const float4* xg = (const float4*)(x + ((size_t)b * T_ * N_ + n) * D_);
        #pragma unroll
        for (int i = tid; i < T_ * D_ / 4; i += 512) {
            const int t  = i >> 5;
            const int c2 = (i & 31) * 2;
            float4 v = xg[(size_t)t * (N_ * D_ / 4) + (i & 31)];
            XA[t * 68 + c2]     = h2pack(v.x, v.y);
            XA[t * 68 + c2 + 1] = h2pack(v.z, v.w);
        }
    }

    // GEMM1 mapping
    const int matId = wid >> 3;              // 0: K-warps, 1: V-warps
    const int k_m0  = (wid & 3) * 16;        // t tile
    const int k_n0  = ((wid >> 2) & 1) * 64; // dc half
    const int v_m0  = (wid & 7) * 16;        // dc tile (V^T rows)
    // att / PV mapping
    const int h     = wid >> 3;
    const int a_m0  = (wid & 3) * 16;
    const int a_n0  = ((wid >> 2) & 1) * 32;
    // GEMM2/3 mapping
    const int g2_m0 = (wid & 3) * 16;
    const int g2_n0 = (wid >> 2) * 32;

    float accv[4][4];
    #pragma unroll
    for (int ni = 0; ni < 4; ++ni)
        #pragma unroll
        for (int c = 0; c < 4; ++c) accv[ni][c] = 0.f;

    for (int slot = 0; slot < K_; ++slot) {
        const int   e  = d_eidx[b][slot];
        const float gg = d_gateg[b][slot];

        // =================== GEMM1: K = x@W0+b0 ; V^T = W1^T@x^T + b1 ===================
        {
            const float* W0g = Wd + ((size_t)(e * 2 + 0) * N_ + n) * (D_ * D_);
            const float* W1g = Wd + ((size_t)(e * 2 + 1) * N_ + n) * (D_ * D_);

            float acc[8][4];
            if (matId == 0) {
                const float* bm = bd + ((size_t)(e * 2 + 0) * N_ + n) * D_;
                #pragma unroll
                for (int ni = 0; ni < 8; ++ni) {
                    const float b0v = bm[k_n0 + 8 * ni + 2 * tq];
                    const float b1v = bm[k_n0 + 8 * ni + 2 * tq + 1];
                    acc[ni][0] = b0v; acc[ni][1] = b1v; acc[ni][2] = b0v; acc[ni][3] = b1v;
                }
            } else {
                const float* bm = bd + ((size_t)(e * 2 + 1) * N_ + n) * D_;
                const float blo = bm[v_m0 + g];
                const float bhi = bm[v_m0 + 8 + g];
                #pragma unroll
                for (int ni = 0; ni < 8; ++ni) {
                    acc[ni][0] = blo; acc[ni][1] = blo; acc[ni][2] = bhi; acc[ni][3] = bhi;
                }
            }
            for (int s = 0; s < 4; ++s) {
                __syncthreads();
                // stage W0,W1 slab s transposed into WS [mat][c][d2local]
                #pragma unroll
                for (int j = tid; j < 4096; j += 512) {
                    const int mat = j >> 11;
                    const int c   = j & 127;
                    const int d2  = (j >> 7) & 15;
                    const float* Wgm = mat ? W1g : W0g;
                    const int dg = s * 32 + 2 * d2;
                    WS[mat * 2560 + c * 20 + d2] =
                        h2pack(Wgm[dg * D_ + c], Wgm[(dg + 1) * D_ + c]);
                }
                __syncthreads();
                #pragma unroll
                for (int kk = 0; kk < 2; ++kk) {
                    if (matId == 0) {
                        const int d2g = s * 16 + kk * 8;
                        u32 a[4];
                        a[0] = XA[(k_m0 + g)     * 68 + d2g + tq];
                        a[1] = XA[(k_m0 + 8 + g) * 68 + d2g + tq];
                        a[2] = XA[(k_m0 + g)     * 68 + d2g + tq + 4];
                        a[3] = XA[(k_m0 + 8 + g) * 68 + d2g + tq + 4];
                        #pragma unroll
                        for (int ni = 0; ni < 8; ++ni) {
                            u32 bf[2];
                            bf[0] = WS[(k_n0 + 8 * ni + g) * 20 + kk * 8 + tq];
                            bf[1] = WS[(k_n0 + 8 * ni + g) * 20 + kk * 8 + tq + 4];
                            mma_f16(acc[ni], a, bf);
                        }
                    } else {
                        const int d2g = s * 16 + kk * 8;
                        u32 a[4];
                        a[0] = WS[2560 + (v_m0 + g)     * 20 + kk * 8 + tq];
                        a[1] = WS[2560 + (v_m0 + 8 + g) * 20 + kk * 8 + tq];
                        a[2] = WS[2560 + (v_m0 + g)     * 20 + kk * 8 + tq + 4];
                        a[3] = WS[2560 + (v_m0 + 8 + g) * 20 + kk * 8 + tq + 4];
                        #pragma unroll
                        for (int ni = 0; ni < 8; ++ni) {
                            u32 bf[2];
                            bf[0] = XA[(8 * ni + g) * 68 + d2g + tq];
                            bf[1] = XA[(8 * ni + g) * 68 + d2g + tq + 4];
                            mma_f16(acc[ni], a, bf);
                        }
                    }
                }
            }
            if (matId == 0) {
                #pragma unroll
                for (int ni = 0; ni < 8; ++ni) {
                    KS[(k_m0 + g)     * 68 + k_n0 / 2 + 4 * ni + tq] = h2pack(acc[ni][0], acc[ni][1]);
                    KS[(k_m0 + 8 + g) * 68 + k_n0 / 2 + 4 * ni + tq] = h2pack(acc[ni][2], acc[ni][3]);
                }
            } else {
                #pragma unroll
                for (int ni = 0; ni < 8; ++ni) {
                    VT[(v_m0 + g)     * 36 + 4 * ni + tq] = h2pack(acc[ni][0], acc[ni][1]);
                    VT[(v_m0 + 8 + g) * 36 + 4 * ni + tq] = h2pack(acc[ni][2], acc[ni][3]);
                }
            }
            __syncthreads();
        }

        // =================== att: S = Q K^T / 8 (per head) ===================
        {
            const int hb2 = h * 32;
            float sa[4][4];
            #pragma unroll
            for (int ni = 0; ni < 4; ++ni)
                #pragma unroll
                for (int c = 0; c < 4; ++c) sa[ni][c] = 0.f;
            #pragma unroll
            for (int ks = 0; ks < 4; ++ks) {
                const int d2g = hb2 + ks * 8;
                u32 a[4];
                a[0] = XA[(a_m0 + g)     * 68 + d2g + tq];
                a[1] = XA[(a_m0 + 8 + g) * 68 + d2g + tq];
                a[2] = XA[(a_m0 + g)     * 68 + d2g + tq + 4];
                a[3] = XA[(a_m0 + 8 + g) * 68 + d2g + tq + 4];
                #pragma unroll
                for (int ni = 0; ni < 4; ++ni) {
                    u32 bf[2];
                    bf[0] = KS[(a_n0 + 8 * ni + g) * 68 + d2g + tq];
                    bf[1] = KS[(a_n0 + 8 * ni + g) * 68 + d2g + tq + 4];
                    mma_f16(sa[ni], a, bf);
                }
            }
            float* Sh = S + h * 4352;
            #pragma unroll
            for (int ni = 0; ni < 4; ++ni) {
                const int cc = a_n0 + 8 * ni + 2 * tq;
                *(u64*)&Sh[(a_m0 + g)     * 68 + cc] = fpack(0.125f * sa[ni][0], 0.125f * sa[ni][1]);
                *(u64*)&Sh[(a_m0 + 8 + g) * 68 + cc] = fpack(0.125f * sa[ni][2], 0.125f * sa[ni][3]);
            }
            __syncthreads();
        }

        // =================== softmax -> P (half) ===================
        {
            __half* Pb = (__half*)PS;
            #pragma unroll
            for (int j = 0; j < 8; ++j) {
                const int r  = wid * 8 + j;
                const int hh = r >> 6;
                const int t  = r & 63;
                float* row = S + hh * 4352 + t * 68;
                const float a0 = row[lane];
                const float a1 = row[lane + 32];
                float m = fmaxf(a0, a1);
                #pragma unroll
                for (int o = 16; o > 0; o >>= 1) m = fmaxf(m, __shfl_xor_sync(0xffffffffu, m, o));
                const float e0 = __expf(a0 - m);
                const float e1 = __expf(a1 - m);
                float sum = e0 + e1;
                #pragma unroll
                for (int o = 16; o > 0; o >>= 1) sum += __shfl_xor_sync(0xffffffffu, sum, o);
                const float inv = 1.0f / sum;
                __half* Ph = Pb + hh * 4608 + t * 72;
                Ph[lane]      = __float2half_rn(e0 * inv);
                Ph[lane + 32] = __float2half_rn(e1 * inv);
            }
            __syncthreads();
        }

        // =================== O = P V (per head) ===================
        {
            const u32* Pu = PS + h * 2304;
            float oa[4][4];
            #pragma unroll
            for (int ni = 0; ni < 4; ++ni)
                #pragma unroll
                for (int c = 0; c < 4; ++c) oa[ni][c] = 0.f;
            #pragma unroll
            for (int ks = 0; ks < 4; ++ks) {
                const int kt2 = ks * 8;
                u32 a[4];
                a[0] = Pu[(a_m0 + g)     * 36 + kt2 + tq];
                a[1] = Pu[(a_m0 + 8 + g) * 36 + kt2 + tq];
                a[2] = Pu[(a_m0 + g)     * 36 + kt2 + tq + 4];
                a[3] = Pu[(a_m0 + 8 + g) * 36 + kt2 + tq + 4];
                #pragma unroll
                for (int ni = 0; ni < 4; ++ni) {
                    u32 bf[2];
                    bf[0] = VT[(h * 64 + a_n0 + 8 * ni + g) * 36 + kt2 + tq];
                    bf[1] = VT[(h * 64 + a_n0 + 8 * ni + g) * 36 + kt2 + tq + 4];
                    mma_f16(oa[ni], a, bf);
                }
            }
            #pragma unroll
            for (int ni = 0; ni < 4; ++ni) {
                const int c2 = h * 32 + a_n0 / 2 + 4 * ni + tq;
                OS[(a_m0 + g)     * 68 + c2] = h2pack(oa[ni][0], oa[ni][1]);
                OS[(a_m0 + 8 + g) * 68 + c2] = h2pack(oa[ni][2], oa[ni][3]);
            }
            __syncthreads();
        }

        // =================== GEMM2: O1 = relu(O @ Ws0 + bs0) ===================
        {
            const float* Wg2 = Ws + (size_t)(e * 2 + 0) * D_ * D_;
            const float* bsp = bs + (e * 2 + 0) * D_;
            float acc[4][4];
            #pragma unroll
            for (int ni = 0; ni < 4; ++ni) {
                const float b0v = bsp[g2_n0 + 8 * ni + 2 * tq];
                const float b1v = bsp[g2_n0 + 8 * ni + 2 * tq + 1];
                acc[ni][0] = b0v; acc[ni][1] = b1v; acc[ni][2] = b0v; acc[ni][3] = b1v;
            }
            for (int s = 0; s < 4; ++s) {
                __syncthreads();
                #pragma unroll
                for (int j = tid; j < 2048; j += 512) {
                    const int c  = j & 127;
                    const int d2 = (j >> 7) & 15;
                    const int dg = s * 32 + 2 * d2;
                    WS[c * 20 + d2] = h2pack(Wg2[dg * D_ + c], Wg2[(dg + 1) * D_ + c]);
                }
                __syncthreads();
                #pragma unroll
                for (int kk = 0; kk < 2; ++kk) {
                    const int d2g = s * 16 + kk * 8;
                    u32 a[4];
                    a[0] = OS[(g2_m0 + g)     * 68 + d2g + tq];
                    a[1] = OS[(g2_m0 + 8 + g) * 68 + d2g + tq];
                    a[2] = OS[(g2_m0 + g)     * 68 + d2g + tq + 4];
                    a[3] = OS[(g2_m0 + 8 + g) * 68 + d2g + tq + 4];
                    #pragma unroll
                    for (int ni = 0; ni < 4; ++ni) {
                        u32 bf[2];
                        bf[0] = WS[(g2_n0 + 8 * ni + g) * 20 + kk * 8 + tq];
                        bf[1] = WS[(g2_n0 + 8 * ni + g) * 20 + kk * 8 + tq + 4];
                        mma_f16(acc[ni], a, bf);
                    }
                }
            }
            #pragma unroll
            for (int ni = 0; ni < 4; ++ni) {
                const int c2 = g2_n0 / 2 + 4 * ni + tq;
                O1[(g2_m0 + g)     * 68 + c2] = h2pack(fmaxf(acc[ni][0], 0.f), fmaxf(acc[ni][1], 0.f));
                O1[(g2_m0 + 8 + g) * 68 + c2] = h2pack(fmaxf(acc[ni][2], 0.f), fmaxf(acc[ni][3], 0.f));
            }
        }

        // =================== GEMM3: out_e = O1 @ Ws1 + bs1 ; accv += g*exp ===================
        {
            const float* Wg3 = Ws + (size_t)(e * 2 + 1) * D_ * D_;
            const float* bsp = bs + (e * 2 + 1) * D_;
            float acc[4][4];
            #pragma unroll
            for (int ni = 0; ni < 4; ++ni) {
                const float b0v = bsp[g2_n0 + 8 * ni + 2 * tq];
                const float b1v = bsp[g2_n0 + 8 * ni + 2 * tq + 1];
                acc[ni][0] = b0v; acc[ni][1] = b1v; acc[ni][2] = b0v; acc[ni][3] = b1v;
            }
            for (int s = 0; s < 4; ++s) {
                __syncthreads();   // also orders O1 stores before mma reads
                #pragma unroll
                for (int j = tid; j < 2048; j += 512) {
                    const int c  = j & 127;
                    const int d2 = (j >> 7) & 15;
                    const int dg = s * 32 + 2 * d2;
                    WS[c * 20 + d2] = h2pack(Wg3[dg * D_ + c], Wg3[(dg + 1) * D_ + c]);
                }
                __syncthreads();
                #pragma unroll
                for (int kk = 0; kk < 2; ++kk) {
                    const int d2g = s * 16 + kk * 8;
                    u32 a[4];
                    a[0] = O1[(g2_m0 + g)     * 68 + d2g + tq];
                    a[1] = O1[(g2_m0 + 8 + g) * 68 + d2g + tq];
                    a[2] = O1[(g2_m0 + g)     * 68 + d2g + tq + 4];
                    a[3] = O1[(g2_m0 + 8 + g) * 68 + d2g + tq + 4];
                    #pragma unroll
                    for (int ni = 0; ni < 4; ++ni) {
                        u32 bf[2];
                        bf[0] = WS[(g2_n0 + 8 * ni + g) * 20 + kk * 8 + tq];
                        bf[1] = WS[(g2_n0 + 8 * ni + g) * 20 + kk * 8 + tq + 4];
                        mma_f16(acc[ni], a, bf);
                    }
                }
            }
            #pragma unroll
            for (int ni = 0; ni < 4; ++ni)
                #pragma unroll
                for (int c = 0; c < 4; ++c)
                    accv[ni][c] += gg * __expf(acc[ni][c]);
            __syncthreads();   // before next expert's staging/stores
        }
    }

    // ---- combine epilogue ----
    const float EPSF = 2.2204460492503131e-16f;
    #pragma unroll
    for (int ni = 0; ni < 4; ++ni) {
        const int cc  = g2_n0 + 8 * ni + 2 * tq;
        const int t0r = g2_m0 + g;
        const int t1r = g2_m0 + 8 + g;
        float v0 = accv[ni][0]; if (v0 == 0.f) v0 = EPSF;
        float v1 = accv[ni][1]; if (v1 == 0.f) v1 = EPSF;
        float v2 = accv[ni][2]; if (v2 == 0.f) v2 = EPSF;
        float v3 = accv[ni][3]; if (v3 == 0.f) v3 = EPSF;
        *(u64*)&out[(((size_t)b * T_ + t0r) * N_ + n) * D_ + cc] = fpack(__logf(v0), __logf(v1));
        *(u64*)&out[(((size_t)b * T_ + t1r) * N_ + n) * D_ + cc] = fpack(__logf(v2), __logf(v3));
    }
}

// ---------------------------------------------------------------------------
// launcher
// ---------------------------------------------------------------------------
extern "C" void kernel_launch(void* const* d_in, const int* in_sizes, int n_in,
                              void* d_out, int out_size) {
    const float* x  = (const float*)d_in[0];
    const float* Wg = (const float*)d_in[1];
    const float* Wd = (const float*)d_in[2];
    const float* bd = (const float*)d_in[3];
    const float* Ws = (const float*)d_in[4];
    const float* bs = (const float*)d_in[5];
    float* out = (float*)d_out;

    const int smem_bytes = SMEM_U * 4; // 161792 B
    cudaFuncSetAttribute(moe_kernel, cudaFuncAttributeMaxDynamicSharedMemorySize, smem_bytes);

    gate_kernel<<<B_, 128>>>(x, Wg);
    dim3 grid(N_, B_);
    moe_kernel<<<grid, 512, smem_bytes>>>(x, Wd, bd, Ws, bs, out);
}

// round 10
// speedup vs baseline: 5.0576x; 1.2733x over previous
#include <cuda_runtime.h>
#include <cuda_fp16.h>
#include <math.h>

#define B_ 32
#define T_ 64
#define N_ 32
#define D_ 128
#define E_ 8
#define K_ 2

typedef unsigned long long u64;
typedef unsigned int u32;

// SMEM u32-unit offsets
#define OFF_XA  0        // x     [64][68]  half2 (d-pairs)
#define OFF_KS  4352     // K     [64][68]  half2 (dc-pairs)
#define OFF_VT  8704     // V^T   [128][36] half2 (t-pairs)
#define OFF_PS  13312    // P     [2][64][36] half2 (kt-pairs)
#define OFF_OS  17920    // O     [64][68]  half2   (S overlays OS+O1)
#define OFF_O1  22272    // O1    [64][68]  half2
#define OFF_WS  26624    // Wslab ping-pong: 2 bufs x 5120 u32
#define SMEM_U  36864    // *4 = 147456 bytes

__device__ int   d_eidx[B_][K_];
__device__ float d_gateg[B_][K_];
__device__ float d_part[B_][32][D_];

__device__ __forceinline__ u64 fpack(float lo, float hi) {
    u64 d; asm("mov.b64 %0, {%1, %2};" : "=l"(d) : "f"(lo), "f"(hi)); return d;
}
__device__ __forceinline__ u32 h2pack(float lo, float hi) {
    __half2 h = __floats2half2_rn(lo, hi);
    return *(u32*)&h;
}
__device__ __forceinline__ void mma_f16(float* c, const u32* a, const u32* b) {
    asm volatile(
        "mma.sync.aligned.m16n8k16.row.col.f32.f16.f16.f32 "
        "{%0,%1,%2,%3}, {%4,%5,%6,%7}, {%8,%9}, {%0,%1,%2,%3};\n"
        : "+f"(c[0]), "+f"(c[1]), "+f"(c[2]), "+f"(c[3])
        : "r"(a[0]), "r"(a[1]), "r"(a[2]), "r"(a[3]), "r"(b[0]), "r"(b[1]));
}

// ---------------------------------------------------------------------------
// Gating stage 1: partial row sums (full-chip parallel, coalesced)
// ---------------------------------------------------------------------------
__global__ void gate_partial(const float* __restrict__ x) {
    const int b   = blockIdx.y;
    const int ch  = blockIdx.x;          // 32 chunks of 64 rows
    const int tid = threadIdx.x;         // 128
    const float* base = x + ((size_t)b * T_ * N_ + ch * 64) * D_;
    float s = 0.f;
    #pragma unroll 8
    for (int r = 0; r < 64; ++r) s += base[r * D_ + tid];
    d_part[b][ch][tid] = s;
}

// ---------------------------------------------------------------------------
// Gating stage 2: combine partials, logits, top-2 softmax
// ---------------------------------------------------------------------------
__global__ void gate_kernel(const float* __restrict__ Wg) {
    const int b   = blockIdx.x;
    const int tid = threadIdx.x;  // 128
    __shared__ float smean[D_];
    __shared__ float slog[E_];

    float s = 0.f;
    #pragma unroll
    for (int c = 0; c < 32; ++c) s += d_part[b][c][tid];
    smean[tid] = s * (1.0f / (float)(T_ * N_));
    __syncthreads();

    if (tid < E_) {
        float l = 0.f;
        for (int d = 0; d < D_; ++d) l += smean[d] * Wg[d * E_ + tid];
        slog[tid] = l;
    }
    __syncthreads();

    if (tid == 0) {
        int i0 = 0; float v0 = slog[0];
        for (int e = 1; e < E_; ++e) if (slog[e] > v0) { v0 = slog[e]; i0 = e; }
        int i1 = -1; float v1 = -3.0e38f;
        for (int e = 0; e < E_; ++e) if (e != i0 && slog[e] > v1) { v1 = slog[e]; i1 = e; }
        const float e1  = expf(v1 - v0);
        const float inv = 1.0f / (1.0f + e1);
        d_eidx[b][0]  = i0; d_eidx[b][1]  = i1;
        d_gateg[b][0] = inv; d_gateg[b][1] = e1 * inv;
    }
}

// ---------------------------------------------------------------------------
// Kernel 2: one CTA per (b,n). 512 threads / 16 warps. fp16 mma m16n8k16,
// ping-pong weight staging (1 barrier/stage, LDG hidden behind mma).
// ---------------------------------------------------------------------------
__global__ __launch_bounds__(512, 1)
void moe_kernel(const float* __restrict__ x,
                const float* __restrict__ Wd,
                const float* __restrict__ bd,
                const float* __restrict__ Ws,
                const float* __restrict__ bs,
                float* __restrict__ out) {
    extern __shared__ u32 smu[];
    u32*   XA = smu + OFF_XA;
    u32*   KS = smu + OFF_KS;
    u32*   VT = smu + OFF_VT;
    u32*   PS = smu + OFF_PS;
    u32*   OS = smu + OFF_OS;
    u32*   O1 = smu + OFF_O1;
    u32*   WS = smu + OFF_WS;
    float* S  = (float*)(smu + OFF_OS);   // overlays OS+O1 (dead during att)

    const int n    = blockIdx.x;
    const int b    = blockIdx.y;
    const int tid  = threadIdx.x;
    const int lane = tid & 31;
    const int wid  = tid >> 5;
    const int g    = lane >> 2;
    const int tq   = lane & 3;

    // ---- load x [T][D] -> XA [t][d2] half2 ----
    {
        const float4* xg = (const float4*)(x + ((size_t)b * T_ * N_ + n) * D_);
        #pragma unroll
        for (int i = tid; i < T_ * D_ / 4; i += 512) {
            const int t  = i >> 5;
            const int c2 = (i & 31) * 2;
            float4 v = xg[(size_t)t * (N_ * D_ / 4) + (i & 31)];
            XA[t * 68 + c2]     = h2pack(v.x, v.y);
            XA[t * 68 + c2 + 1] = h2pack(v.z, v.w);
        }
    }

    // GEMM1 mapping
    const int matId = wid >> 3;              // 0: K-warps, 1: V-warps
    const int k_m0  = (wid & 3) * 16;
    const int k_n0  = ((wid >> 2) & 1) * 64;
    const int v_m0  = (wid & 7) * 16;
    // att / PV mapping
    const int h     = wid >> 3;
    const int a_m0  = (wid & 3) * 16;
    const int a_n0  = ((wid >> 2) & 1) * 32;
    // GEMM2/3 mapping
    const int g2_m0 = (wid & 3) * 16;
    const int g2_n0 = (wid >> 2) * 32;

    float accv[4][4];
    #pragma unroll
    for (int ni = 0; ni < 4; ++ni)
        #pragma unroll
        for (int c = 0; c < 4; ++c) accv[ni][c] = 0.f;

    for (int slot = 0; slot < K_; ++slot) {
        const int   e  = d_eidx[b][slot];
        const float gg = d_gateg[b][slot];

        // =================== GEMM1: K = x@W0+b0 ; V^T = W1^T@x^T + b1 ===================
        {
            const float* W0g = Wd + ((size_t)(e * 2 + 0) * N_ + n) * (D_ * D_);
            const float* W1g = Wd + ((size_t)(e * 2 + 1) * N_ + n) * (D_ * D_);

            float acc[8][4];
            if (matId == 0) {
                const float* bm = bd + ((size_t)(e * 2 + 0) * N_ + n) * D_;
                #pragma unroll
                for (int ni = 0; ni < 8; ++ni) {
                    const float b0v = bm[k_n0 + 8 * ni + 2 * tq];
                    const float b1v = bm[k_n0 + 8 * ni + 2 * tq + 1];
                    acc[ni][0] = b0v; acc[ni][1] = b1v; acc[ni][2] = b0v; acc[ni][3] = b1v;
                }
            } else {
                const float* bm = bd + ((size_t)(e * 2 + 1) * N_ + n) * D_;
                const float blo = bm[v_m0 + g];
                const float bhi = bm[v_m0 + 8 + g];
                #pragma unroll
                for (int ni = 0; ni < 8; ++ni) {
                    acc[ni][0] = blo; acc[ni][1] = blo; acc[ni][2] = bhi; acc[ni][3] = bhi;
                }
            }
            // prologue: stage slab 0 into buf0
            #pragma unroll
            for (int j = tid; j < 4096; j += 512) {
                const int mat = j >> 11;
                const int c   = j & 127;
                const int d2  = (j >> 7) & 15;
                const float* Wgm = mat ? W1g : W0g;
                const int dg = 2 * d2;
                WS[mat * 2560 + c * 20 + d2] =
                    h2pack(Wgm[dg * D_ + c], Wgm[(dg + 1) * D_ + c]);
            }
            __syncthreads();
            for (int s = 0; s < 4; ++s) {
                const u32* cur = WS + (s & 1) * 5120;
                u32*       nxt = WS + ((s + 1) & 1) * 5120;
                if (s < 3) {
                    const int sn = s + 1;
                    #pragma unroll
                    for (int j = tid; j < 4096; j += 512) {
                        const int mat = j >> 11;
                        const int c   = j & 127;
                        const int d2  = (j >> 7) & 15;
                        const float* Wgm = mat ? W1g : W0g;
                        const int dg = sn * 32 + 2 * d2;
                        nxt[mat * 2560 + c * 20 + d2] =
                            h2pack(Wgm[dg * D_ + c], Wgm[(dg + 1) * D_ + c]);
                    }
                }
                #pragma unroll
                for (int kk = 0; kk < 2; ++kk) {
                    const int d2g = s * 16 + kk * 8;
                    if (matId == 0) {
                        u32 a[4];
                        a[0] = XA[(k_m0 + g)     * 68 + d2g + tq];
                        a[1] = XA[(k_m0 + 8 + g) * 68 + d2g + tq];
                        a[2] = XA[(k_m0 + g)     * 68 + d2g + tq + 4];
                        a[3] = XA[(k_m0 + 8 + g) * 68 + d2g + tq + 4];
                        #pragma unroll
                        for (int ni = 0; ni < 8; ++ni) {
                            u32 bf[2];
                            bf[0] = cur[(k_n0 + 8 * ni + g) * 20 + kk * 8 + tq];
                            bf[1] = cur[(k_n0 + 8 * ni + g) * 20 + kk * 8 + tq + 4];
                            mma_f16(acc[ni], a, bf);
                        }
                    } else {
                        u32 a[4];
                        a[0] = cur[2560 + (v_m0 + g)     * 20 + kk * 8 + tq];
                        a[1] = cur[2560 + (v_m0 + 8 + g) * 20 + kk * 8 + tq];
                        a[2] = cur[2560 + (v_m0 + g)     * 20 + kk * 8 + tq + 4];
                        a[3] = cur[2560 + (v_m0 + 8 + g) * 20 + kk * 8 + tq + 4];
                        #pragma unroll
                        for (int ni = 0; ni < 8; ++ni) {
                            u32 bf[2];
                            bf[0] = XA[(8 * ni + g) * 68 + d2g + tq];
                            bf[1] = XA[(8 * ni + g) * 68 + d2g + tq + 4];
                            mma_f16(acc[ni], a, bf);
                        }
                    }
                }
                __syncthreads();
            }
            if (matId == 0) {
                #pragma unroll
                for (int ni = 0; ni < 8; ++ni) {
                    KS[(k_m0 + g)     * 68 + k_n0 / 2 + 4 * ni + tq] = h2pack(acc[ni][0], acc[ni][1]);
                    KS[(k_m0 + 8 + g) * 68 + k_n0 / 2 + 4 * ni + tq] = h2pack(acc[ni][2], acc[ni][3]);
                }
            } else {
                #pragma unroll
                for (int ni = 0; ni < 8; ++ni) {
                    VT[(v_m0 + g)     * 36 + 4 * ni + tq] = h2pack(acc[ni][0], acc[ni][1]);
                    VT[(v_m0 + 8 + g) * 36 + 4 * ni + tq] = h2pack(acc[ni][2], acc[ni][3]);
                }
            }
            __syncthreads();
        }

        // =================== att: S = Q K^T / 8 (per head) ===================
        {
            const int hb2 = h * 32;
            float sa[4][4];
            #pragma unroll
            for (int ni = 0; ni < 4; ++ni)
                #pragma unroll
                for (int c = 0; c < 4; ++c) sa[ni][c] = 0.f;
            #pragma unroll
            for (int ks = 0; ks < 4; ++ks) {
                const int d2g = hb2 + ks * 8;
                u32 a[4];
                a[0] = XA[(a_m0 + g)     * 68 + d2g + tq];
                a[1] = XA[(a_m0 + 8 + g) * 68 + d2g + tq];
                a[2] = XA[(a_m0 + g)     * 68 + d2g + tq + 4];
                a[3] = XA[(a_m0 + 8 + g) * 68 + d2g + tq + 4];
                #pragma unroll
                for (int ni = 0; ni < 4; ++ni) {
                    u32 bf[2];
                    bf[0] = KS[(a_n0 + 8 * ni + g) * 68 + d2g + tq];
                    bf[1] = KS[(a_n0 + 8 * ni + g) * 68 + d2g + tq + 4];
                    mma_f16(sa[ni], a, bf);
                }
            }
            float* Sh = S + h * 4352;
            #pragma unroll
            for (int ni = 0; ni < 4; ++ni) {
                const int cc = a_n0 + 8 * ni + 2 * tq;
                *(u64*)&Sh[(a_m0 + g)     * 68 + cc] = fpack(0.125f * sa[ni][0], 0.125f * sa[ni][1]);
                *(u64*)&Sh[(a_m0 + 8 + g) * 68 + cc] = fpack(0.125f * sa[ni][2], 0.125f * sa[ni][3]);
            }
            __syncthreads();
        }

        // =================== softmax -> P (half) ===================
        {
            __half* Pb = (__half*)PS;
            #pragma unroll
            for (int j = 0; j < 8; ++j) {
                const int r  = wid * 8 + j;
                const int hh = r >> 6;
                const int t  = r & 63;
                float* row = S + hh * 4352 + t * 68;
                const float a0 = row[lane];
                const float a1 = row[lane + 32];
                float m = fmaxf(a0, a1);
                #pragma unroll
                for (int o = 16; o > 0; o >>= 1) m = fmaxf(m, __shfl_xor_sync(0xffffffffu, m, o));
                const float e0 = __expf(a0 - m);
                const float e1 = __expf(a1 - m);
                float sum = e0 + e1;
                #pragma unroll
                for (int o = 16; o > 0; o >>= 1) sum += __shfl_xor_sync(0xffffffffu, sum, o);
                const float inv = 1.0f / sum;
                __half* Ph = Pb + hh * 4608 + t * 72;
                Ph[lane]      = __float2half_rn(e0 * inv);
                Ph[lane + 32] = __float2half_rn(e1 * inv);
            }
            __syncthreads();
        }

        // =================== O = P V (per head) ===================
        {
            const u32* Pu = PS + h * 2304;
            float oa[4][4];
            #pragma unroll
            for (int ni = 0; ni < 4; ++ni)
                #pragma unroll
                for (int c = 0; c < 4; ++c) oa[ni][c] = 0.f;
            #pragma unroll
            for (int ks = 0; ks < 4; ++ks) {
                const int kt2 = ks * 8;
                u32 a[4];
                a[0] = Pu[(a_m0 + g)     * 36 + kt2 + tq];
                a[1] = Pu[(a_m0 + 8 + g) * 36 + kt2 + tq];
                a[2] = Pu[(a_m0 + g)     * 36 + kt2 + tq + 4];
                a[3] = Pu[(a_m0 + 8 + g) * 36 + kt2 + tq + 4];
                #pragma unroll
                for (int ni = 0; ni < 4; ++ni) {
                    u32 bf[2];
                    bf[0] = VT[(h * 64 + a_n0 + 8 * ni + g) * 36 + kt2 + tq];
                    bf[1] = VT[(h * 64 + a_n0 + 8 * ni + g) * 36 + kt2 + tq + 4];
                    mma_f16(oa[ni], a, bf);
                }
            }
            __syncthreads();   // S reads done before OS overwrite (overlay!)
            #pragma unroll
            for (int ni = 0; ni < 4; ++ni) {
                const int c2 = h * 32 + a_n0 / 2 + 4 * ni + tq;
                OS[(a_m0 + g)     * 68 + c2] = h2pack(oa[ni][0], oa[ni][1]);
                OS[(a_m0 + 8 + g) * 68 + c2] = h2pack(oa[ni][2], oa[ni][3]);
            }
            __syncthreads();
        }

        // =================== GEMM2: O1 = relu(O @ Ws0 + bs0) ===================
        {
            const float* Wg2 = Ws + (size_t)(e * 2 + 0) * D_ * D_;
            const float* bsp = bs + (e * 2 + 0) * D_;
            float acc[4][4];
            #pragma unroll
            for (int ni = 0; ni < 4; ++ni) {
                const float b0v = bsp[g2_n0 + 8 * ni + 2 * tq];
                const float b1v = bsp[g2_n0 + 8 * ni + 2 * tq + 1];
                acc[ni][0] = b0v; acc[ni][1] = b1v; acc[ni][2] = b0v; acc[ni][3] = b1v;
            }
            #pragma unroll
            for (int j = tid; j < 2048; j += 512) {
                const int c  = j & 127;
                const int d2 = (j >> 7) & 15;
                const int dg = 2 * d2;
                WS[c * 20 + d2] = h2pack(Wg2[dg * D_ + c], Wg2[(dg + 1) * D_ + c]);
            }
            __syncthreads();
            for (int s = 0; s < 4; ++s) {
                const u32* cur = WS + (s & 1) * 5120;
                u32*       nxt = WS + ((s + 1) & 1) * 5120;
                if (s < 3) {
                    const int sn = s + 1;
                    #pragma unroll
                    for (int j = tid; j < 2048; j += 512) {
                        const int c  = j & 127;
                        const int d2 = (j >> 7) & 15;
                        const int dg = sn * 32 + 2 * d2;
                        nxt[c * 20 + d2] = h2pack(Wg2[dg * D_ + c], Wg2[(dg + 1) * D_ + c]);
                    }
                }
                #pragma unroll
                for (int kk = 0; kk < 2; ++kk) {
                    const int d2g = s * 16 + kk * 8;
                    u32 a[4];
                    a[0] = OS[(g2_m0 + g)     * 68 + d2g + tq];
                    a[1] = OS[(g2_m0 + 8 + g) * 68 + d2g + tq];
                    a[2] = OS[(g2_m0 + g)     * 68 + d2g + tq + 4];
                    a[3] = OS[(g2_m0 + 8 + g) * 68 + d2g + tq + 4];
                    #pragma unroll
                    for (int ni = 0; ni < 4; ++ni) {
                        u32 bf[2];
                        bf[0] = cur[(g2_n0 + 8 * ni + g) * 20 + kk * 8 + tq];
                        bf[1] = cur[(g2_n0 + 8 * ni + g) * 20 + kk * 8 + tq + 4];
                        mma_f16(acc[ni], a, bf);
                    }
                }
                __syncthreads();
            }
            #pragma unroll
            for (int ni = 0; ni < 4; ++ni) {
                const int c2 = g2_n0 / 2 + 4 * ni + tq;
                O1[(g2_m0 + g)     * 68 + c2] = h2pack(fmaxf(acc[ni][0], 0.f), fmaxf(acc[ni][1], 0.f));
                O1[(g2_m0 + 8 + g) * 68 + c2] = h2pack(fmaxf(acc[ni][2], 0.f), fmaxf(acc[ni][3], 0.f));
            }
        }

        // =================== GEMM3: out_e = O1 @ Ws1 + bs1 ; accv += g*exp ===================
        {
            const float* Wg3 = Ws + (size_t)(e * 2 + 1) * D_ * D_;
            const float* bsp = bs + (e * 2 + 1) * D_;
            float acc[4][4];
            #pragma unroll
            for (int ni = 0; ni < 4; ++ni) {
                const float b0v = bsp[g2_n0 + 8 * ni + 2 * tq];
                const float b1v = bsp[g2_n0 + 8 * ni + 2 * tq + 1];
                acc[ni][0] = b0v; acc[ni][1] = b1v; acc[ni][2] = b0v; acc[ni][3] = b1v;
            }
            #pragma unroll
            for (int j = tid; j < 2048; j += 512) {
                const int c  = j & 127;
                const int d2 = (j >> 7) & 15;
                const int dg = 2 * d2;
                WS[c * 20 + d2] = h2pack(Wg3[dg * D_ + c], Wg3[(dg + 1) * D_ + c]);
            }
            __syncthreads();   // orders O1 stores + staging before compute
            for (int s = 0; s < 4; ++s) {
                const u32* cur = WS + (s & 1) * 5120;
                u32*       nxt = WS + ((s + 1) & 1) * 5120;
                if (s < 3) {
                    const int sn = s + 1;
                    #pragma unroll
                    for (int j = tid; j < 2048; j += 512) {
                        const int c  = j & 127;
                        const int d2 = (j >> 7) & 15;
                        const int dg = sn * 32 + 2 * d2;
                        nxt[c * 20 + d2] = h2pack(Wg3[dg * D_ + c], Wg3[(dg + 1) * D_ + c]);
                    }
                }
                #pragma unroll
                for (int kk = 0; kk < 2; ++kk) {
                    const int d2g = s * 16 + kk * 8;
                    u32 a[4];
                    a[0] = O1[(g2_m0 + g)     * 68 + d2g + tq];
                    a[1] = O1[(g2_m0 + 8 + g) * 68 + d2g + tq];
                    a[2] = O1[(g2_m0 + g)     * 68 + d2g + tq + 4];
                    a[3] = O1[(g2_m0 + 8 + g) * 68 + d2g + tq + 4];
                    #pragma unroll
                    for (int ni = 0; ni < 4; ++ni) {
                        u32 bf[2];
                        bf[0] = cur[(g2_n0 + 8 * ni + g) * 20 + kk * 8 + tq];
                        bf[1] = cur[(g2_n0 + 8 * ni + g) * 20 + kk * 8 + tq + 4];
                        mma_f16(acc[ni], a, bf);
                    }
                }
                __syncthreads();
            }
            #pragma unroll
            for (int ni = 0; ni < 4; ++ni)
                #pragma unroll
                for (int c = 0; c < 4; ++c)
                    accv[ni][c] += gg * __expf(acc[ni][c]);
        }
    }

    // ---- combine epilogue ----
    const float EPSF = 2.2204460492503131e-16f;
    #pragma unroll
    for (int ni = 0; ni < 4; ++ni) {
        const int cc  = g2_n0 + 8 * ni + 2 * tq;
        const int t0r = g2_m0 + g;
        const int t1r = g2_m0 + 8 + g;
        float v0 = accv[ni][0]; if (v0 == 0.f) v0 = EPSF;
        float v1 = accv[ni][1]; if (v1 == 0.f) v1 = EPSF;
        float v2 = accv[ni][2]; if (v2 == 0.f) v2 = EPSF;
        float v3 = accv[ni][3]; if (v3 == 0.f) v3 = EPSF;
        *(u64*)&out[(((size_t)b * T_ + t0r) * N_ + n) * D_ + cc] = fpack(__logf(v0), __logf(v1));
        *(u64*)&out[(((size_t)b * T_ + t1r) * N_ + n) * D_ + cc] = fpack(__logf(v2), __logf(v3));
    }
}

// ---------------------------------------------------------------------------
// launcher
// ---------------------------------------------------------------------------
extern "C" void kernel_launch(void* const* d_in, const int* in_sizes, int n_in,
                              void* d_out, int out_size) {
    const float* x  = (const float*)d_in[0];
    const float* Wg = (const float*)d_in[1];
    const float* Wd = (const float*)d_in[2];
    const float* bd = (const float*)d_in[3];
    const float* Ws = (const float*)d_in[4];
    const float* bs = (const float*)d_in[5];
    float* out = (float*)d_out;

    const int smem_bytes = SMEM_U * 4; // 147456 B
    cudaFuncSetAttribute(moe_kernel, cudaFuncAttributeMaxDynamicSharedMemorySize, smem_bytes);

    dim3 pgrid(32, B_);
    gate_partial<<<pgrid, 128>>>(x);
    gate_kernel<<<B_, 128>>>(Wg);
    dim3 grid(N_, B_);
    moe_kernel<<<grid, 512, smem_bytes>>>(x, Wd, bd, Ws, bs, out);
}

// round 11
// speedup vs baseline: 6.0751x; 1.2012x over previous
#include <cuda_runtime.h>
#include <cuda_fp16.h>
#include <math.h>

#define B_ 32
#define T_ 64
#define N_ 32
#define D_ 128
#define E_ 8
#define K_ 2

typedef unsigned long long u64;
typedef unsigned int u32;

// SMEM u32-unit offsets
#define OFF_XA  0        // x     [64][68]  half2 (d-pairs)
#define OFF_KS  4352     // K     [64][68]  half2 (dc-pairs)
#define OFF_VT  8704     // V^T   [128][36] half2 (t-pairs)
#define OFF_PS  13312    // P     [2][64][36] half2 (kt-pairs)
#define OFF_OS  17920    // O     [64][68]  half2   (S overlays OS+O1)
#define OFF_O1  22272    // O1    [64][68]  half2
#define OFF_WS  26624    // Wslab ping-pong: 2 bufs x 5120 u32
#define SMEM_U  36864    // *4 = 147456 bytes

__device__ int   d_eidx[B_][K_];
__device__ float d_gateg[B_][K_];
__device__ float d_part[B_][32][D_];

// Pre-converted fp16 weights in staging-buffer layout:
// WdT_g[e][n][s][mat*2560 + c*20 + d2]   (5120 u32 per (e,n,s))
// WsT_g[(e*2+mat)][s][c*20 + d2]         (2560 u32 per (e,mat,s))
__device__ u32 WdT_g[8 * 32 * 4 * 5120];   // ~21 MB
__device__ u32 WsT_g[16 * 4 * 2560];       // 640 KB

__device__ __forceinline__ u64 fpack(float lo, float hi) {
    u64 d; asm("mov.b64 %0, {%1, %2};" : "=l"(d) : "f"(lo), "f"(hi)); return d;
}
__device__ __forceinline__ u32 h2pack(float lo, float hi) {
    __half2 h = __floats2half2_rn(lo, hi);
    return *(u32*)&h;
}
__device__ __forceinline__ void mma_f16(float* c, const u32* a, const u32* b) {
    asm volatile(
        "mma.sync.aligned.m16n8k16.row.col.f32.f16.f16.f32 "
        "{%0,%1,%2,%3}, {%4,%5,%6,%7}, {%8,%9}, {%0,%1,%2,%3};\n"
        : "+f"(c[0]), "+f"(c[1]), "+f"(c[2]), "+f"(c[3])
        : "r"(a[0]), "r"(a[1]), "r"(a[2]), "r"(a[3]), "r"(b[0]), "r"(b[1]));
}
__device__ __forceinline__ void cp16(u32 smem_addr, const void* gptr) {
    asm volatile("cp.async.cg.shared.global [%0], [%1], 16;" :: "r"(smem_addr), "l"(gptr));
}
#define CP_COMMIT() asm volatile("cp.async.commit_group;")

// ---------------------------------------------------------------------------
// Prep: convert fp32 weights -> fp16 half2 staging layout (once per launch)
// ---------------------------------------------------------------------------
__global__ void prep_kernel(const float* __restrict__ Wd,
                            const float* __restrict__ Ws) {
    __shared__ float tile[32][129];
    const int bid = blockIdx.x;
    const int tid = threadIdx.x;   // 256
    const float* src;
    u32* dst;
    if (bid < 2048) {
        const int s = bid & 3, mat = (bid >> 2) & 1, n = (bid >> 3) & 31, e = bid >> 8;
        src = Wd + ((size_t)(e * 2 + mat) * 32 + n) * (128 * 128) + s * 32 * 128;
        dst = WdT_g + ((size_t)((e * 32 + n) * 4 + s)) * 5120 + mat * 2560;
    } else {
        const int r = bid - 2048;  // 0..63
        const int s = r & 3, em = r >> 2;   // em = e*2+mat
        src = Ws + (size_t)em * (128 * 128) + s * 32 * 128;
        dst = WsT_g + ((size_t)em * 4 + s) * 2560;
    }
    #pragma unroll
    for (int i = tid; i < 4096; i += 256)
        tile[i >> 7][i & 127] = src[i];
    __syncthreads();
    for (int j = tid; j < 2560; j += 256) {
        const int c = j / 20, d2 = j % 20;
        u32 v = 0;
        if (d2 < 16) v = h2pack(tile[2 * d2][c], tile[2 * d2 + 1][c]);
        dst[j] = v;
    }
}

// ---------------------------------------------------------------------------
// Gating stage 1: partial row sums
// ---------------------------------------------------------------------------
__global__ void gate_partial(const float* __restrict__ x) {
    const int b   = blockIdx.y;
    const int ch  = blockIdx.x;
    const int tid = threadIdx.x;   // 128
    const float* base = x + ((size_t)b * T_ * N_ + ch * 64) * D_;
    float s = 0.f;
    #pragma unroll 8
    for (int r = 0; r < 64; ++r) s += base[r * D_ + tid];
    d_part[b][ch][tid] = s;
}

// ---------------------------------------------------------------------------
// Gating stage 2: combine, logits, top-2 softmax
// ---------------------------------------------------------------------------
__global__ void gate_kernel(const float* __restrict__ Wg) {
    const int b   = blockIdx.x;
    const int tid = threadIdx.x;   // 128
    __shared__ float smean[D_];
    __shared__ float slog[E_];

    float s = 0.f;
    #pragma unroll
    for (int c = 0; c < 32; ++c) s += d_part[b][c][tid];
    smean[tid] = s * (1.0f / (float)(T_ * N_));
    __syncthreads();

    if (tid < E_) {
        float l = 0.f;
        for (int d = 0; d < D_; ++d) l += smean[d] * Wg[d * E_ + tid];
        slog[tid] = l;
    }
    __syncthreads();

    if (tid == 0) {
        int i0 = 0; float v0 = slog[0];
        for (int e = 1; e < E_; ++e) if (slog[e] > v0) { v0 = slog[e]; i0 = e; }
        int i1 = -1; float v1 = -3.0e38f;
        for (int e = 0; e < E_; ++e) if (e != i0 && slog[e] > v1) { v1 = slog[e]; i1 = e; }
        const float e1  = expf(v1 - v0);
        const float inv = 1.0f / (1.0f + e1);
        d_eidx[b][0]  = i0; d_eidx[b][1]  = i1;
        d_gateg[b][0] = inv; d_gateg[b][1] = e1 * inv;
    }
}

// ---------------------------------------------------------------------------
// Kernel 2: one CTA per (b,n). fp16 mma m16n8k16; weight staging is pure
// cp.async from pre-converted global layout, double-buffered.
// ---------------------------------------------------------------------------
__global__ __launch_bounds__(512, 1)
void moe_kernel(const float* __restrict__ x,
                const float* __restrict__ bd,
                const float* __restrict__ bs,
                float* __restrict__ out) {
    extern __shared__ u32 smu[];
    u32*   XA = smu + OFF_XA;
    u32*   KS = smu + OFF_KS;
    u32*   VT = smu + OFF_VT;
    u32*   PS = smu + OFF_PS;
    u32*   OS = smu + OFF_OS;
    u32*   O1 = smu + OFF_O1;
    u32*   WS = smu + OFF_WS;
    float* S  = (float*)(smu + OFF_OS);

    const u32 ws_smem = (u32)__cvta_generic_to_shared(WS);

    const int n    = blockIdx.x;
    const int b    = blockIdx.y;
    const int tid  = threadIdx.x;
    const int lane = tid & 31;
    const int wid  = tid >> 5;
    const int g    = lane >> 2;
    const int tq   = lane & 3;

    // ---- load x [T][D] -> XA half2 ----
    {
        const float4* xg = (const float4*)(x + ((size_t)b * T_ * N_ + n) * D_);
        #pragma unroll
        for (int i = tid; i < T_ * D_ / 4; i += 512) {
            const int t  = i >> 5;
            const int c2 = (i & 31) * 2;
            float4 v = xg[(size_t)t * (N_ * D_ / 4) + (i & 31)];
            XA[t * 68 + c2]     = h2pack(v.x, v.y);
            XA[t * 68 + c2 + 1] = h2pack(v.z, v.w);
        }
    }

    // mappings
    const int matId = wid >> 3;
    const int k_m0  = (wid & 3) * 16;
    const int k_n0  = ((wid >> 2) & 1) * 64;
    const int v_m0  = (wid & 7) * 16;
    const int h     = wid >> 3;
    const int a_m0  = (wid & 3) * 16;
    const int a_n0  = ((wid >> 2) & 1) * 32;
    const int g2_m0 = (wid & 3) * 16;
    const int g2_n0 = (wid >> 2) * 32;

    float accv[4][4];
    #pragma unroll
    for (int ni = 0; ni < 4; ++ni)
        #pragma unroll
        for (int c = 0; c < 4; ++c) accv[ni][c] = 0.f;

    for (int slot = 0; slot < K_; ++slot) {
        const int   e  = d_eidx[b][slot];
        const float gg = d_gateg[b][slot];

        // =================== GEMM1: K = x@W0+b0 ; V^T = W1^T@x^T + b1 ===================
        {
            const u32* wdsrc = WdT_g + ((size_t)(e * 32 + n) * 4) * 5120;

            float acc[8][4];
            if (matId == 0) {
                const float* bm = bd + ((size_t)(e * 2 + 0) * N_ + n) * D_;
                #pragma unroll
                for (int ni = 0; ni < 8; ++ni) {
                    const float b0v = bm[k_n0 + 8 * ni + 2 * tq];
                    const float b1v = bm[k_n0 + 8 * ni + 2 * tq + 1];
                    acc[ni][0] = b0v; acc[ni][1] = b1v; acc[ni][2] = b0v; acc[ni][3] = b1v;
                }
            } else {
                const float* bm = bd + ((size_t)(e * 2 + 1) * N_ + n) * D_;
                const float blo = bm[v_m0 + g];
                const float bhi = bm[v_m0 + 8 + g];
                #pragma unroll
                for (int ni = 0; ni < 8; ++ni) {
                    acc[ni][0] = blo; acc[ni][1] = blo; acc[ni][2] = bhi; acc[ni][3] = bhi;
                }
            }
            // prologue: stage slab 0 into buf0 (pure cp.async)
            #pragma unroll
            for (int j = tid; j < 1280; j += 512)
                cp16(ws_smem + (u32)(j * 16), wdsrc + j * 4);
            CP_COMMIT();
            for (int s = 0; s < 4; ++s) {
                const u32* cur = WS + (s & 1) * 5120;
                if (s < 3) {
                    const u32 boff = (u32)(((s + 1) & 1) * 5120 * 4);
                    const u32* src = wdsrc + (s + 1) * 5120;
                    #pragma unroll
                    for (int j = tid; j < 1280; j += 512)
                        cp16(ws_smem + boff + (u32)(j * 16), src + j * 4);
                    CP_COMMIT();
                    asm volatile("cp.async.wait_group 1;");
                } else {
                    asm volatile("cp.async.wait_group 0;");
                }
                __syncthreads();
                #pragma unroll
                for (int kk = 0; kk < 2; ++kk) {
                    const int d2g = s * 16 + kk * 8;
                    if (matId == 0) {
                        u32 a[4];
                        a[0] = XA[(k_m0 + g)     * 68 + d2g + tq];
                        a[1] = XA[(k_m0 + 8 + g) * 68 + d2g + tq];
                        a[2] = XA[(k_m0 + g)     * 68 + d2g + tq + 4];
                        a[3] = XA[(k_m0 + 8 + g) * 68 + d2g + tq + 4];
                        #pragma unroll
                        for (int ni = 0; ni < 8; ++ni) {
                            u32 bf[2];
                            bf[0] = cur[(k_n0 + 8 * ni + g) * 20 + kk * 8 + tq];
                            bf[1] = cur[(k_n0 + 8 * ni + g) * 20 + kk * 8 + tq + 4];
                            mma_f16(acc[ni], a, bf);
                        }
                    } else {
                        u32 a[4];
                        a[0] = cur[2560 + (v_m0 + g)     * 20 + kk * 8 + tq];
                        a[1] = cur[2560 + (v_m0 + 8 + g) * 20 + kk * 8 + tq];
                        a[2] = cur[2560 + (v_m0 + g)     * 20 + kk * 8 + tq + 4];
                        a[3] = cur[2560 + (v_m0 + 8 + g) * 20 + kk * 8 + tq + 4];
                        #pragma unroll
                        for (int ni = 0; ni < 8; ++ni) {
                            u32 bf[2];
                            bf[0] = XA[(8 * ni + g) * 68 + d2g + tq];
                            bf[1] = XA[(8 * ni + g) * 68 + d2g + tq + 4];
                            mma_f16(acc[ni], a, bf);
                        }
                    }
                }
                __syncthreads();
            }
            if (matId == 0) {
                #pragma unroll
                for (int ni = 0; ni < 8; ++ni) {
                    KS[(k_m0 + g)     * 68 + k_n0 / 2 + 4 * ni + tq] = h2pack(acc[ni][0], acc[ni][1]);
                    KS[(k_m0 + 8 + g) * 68 + k_n0 / 2 + 4 * ni + tq] = h2pack(acc[ni][2], acc[ni][3]);
                }
            } else {
                #pragma unroll
                for (int ni = 0; ni < 8; ++ni) {
                    VT[(v_m0 + g)     * 36 + 4 * ni + tq] = h2pack(acc[ni][0], acc[ni][1]);
                    VT[(v_m0 + 8 + g) * 36 + 4 * ni + tq] = h2pack(acc[ni][2], acc[ni][3]);
                }
            }
            __syncthreads();
        }

        // =================== att: S = Q K^T / 8 (per head) ===================
        {
            const int hb2 = h * 32;
            float sa[4][4];
            #pragma unroll
            for (int ni = 0; ni < 4; ++ni)
                #pragma unroll
                for (int c = 0; c < 4; ++c) sa[ni][c] = 0.f;
            #pragma unroll
            for (int ks = 0; ks < 4; ++ks) {
                const int d2g = hb2 + ks * 8;
                u32 a[4];
                a[0] = XA[(a_m0 + g)     * 68 + d2g + tq];
                a[1] = XA[(a_m0 + 8 + g) * 68 + d2g + tq];
                a[2] = XA[(a_m0 + g)     * 68 + d2g + tq + 4];
                a[3] = XA[(a_m0 + 8 + g) * 68 + d2g + tq + 4];
                #pragma unroll
                for (int ni = 0; ni < 4; ++ni) {
                    u32 bf[2];
                    bf[0] = KS[(a_n0 + 8 * ni + g) * 68 + d2g + tq];
                    bf[1] = KS[(a_n0 + 8 * ni + g) * 68 + d2g + tq + 4];
                    mma_f16(sa[ni], a, bf);
                }
            }
            float* Sh = S + h * 4352;
            #pragma unroll
            for (int ni = 0; ni < 4; ++ni) {
                const int cc = a_n0 + 8 * ni + 2 * tq;
                *(u64*)&Sh[(a_m0 + g)     * 68 + cc] = fpack(0.125f * sa[ni][0], 0.125f * sa[ni][1]);
                *(u64*)&Sh[(a_m0 + 8 + g) * 68 + cc] = fpack(0.125f * sa[ni][2], 0.125f * sa[ni][3]);
            }
            __syncthreads();
        }

        // =================== softmax -> P (half) ===================
        {
            __half* Pb = (__half*)PS;
            #pragma unroll
            for (int j = 0; j < 8; ++j) {
                const int r  = wid * 8 + j;
                const int hh = r >> 6;
                const int t  = r & 63;
                float* row = S + hh * 4352 + t * 68;
                const float a0 = row[lane];
                const float a1 = row[lane + 32];
                float m = fmaxf(a0, a1);
                #pragma unroll
                for (int o = 16; o > 0; o >>= 1) m = fmaxf(m, __shfl_xor_sync(0xffffffffu, m, o));
                const float e0 = __expf(a0 - m);
                const float e1 = __expf(a1 - m);
                float sum = e0 + e1;
                #pragma unroll
                for (int o = 16; o > 0; o >>= 1) sum += __shfl_xor_sync(0xffffffffu, sum, o);
                const float inv = 1.0f / sum;
                __half* Ph = Pb + hh * 4608 + t * 72;
                Ph[lane]      = __float2half_rn(e0 * inv);
                Ph[lane + 32] = __float2half_rn(e1 * inv);
            }
            __syncthreads();
        }

        // =================== O = P V (per head) ===================
        {
            const u32* Pu = PS + h * 2304;
            float oa[4][4];
            #pragma unroll
            for (int ni = 0; ni < 4; ++ni)
                #pragma unroll
                for (int c = 0; c < 4; ++c) oa[ni][c] = 0.f;
            #pragma unroll
            for (int ks = 0; ks < 4; ++ks) {
                const int kt2 = ks * 8;
                u32 a[4];
                a[0] = Pu[(a_m0 + g)     * 36 + kt2 + tq];
                a[1] = Pu[(a_m0 + 8 + g) * 36 + kt2 + tq];
                a[2] = Pu[(a_m0 + g)     * 36 + kt2 + tq + 4];
                a[3] = Pu[(a_m0 + 8 + g) * 36 + kt2 + tq + 4];
                #pragma unroll
                for (int ni = 0; ni < 4; ++ni) {
                    u32 bf[2];
                    bf[0] = VT[(h * 64 + a_n0 + 8 * ni + g) * 36 + kt2 + tq];
                    bf[1] = VT[(h * 64 + a_n0 + 8 * ni + g) * 36 + kt2 + tq + 4];
                    mma_f16(oa[ni], a, bf);
                }
            }
            __syncthreads();   // S reads done before OS overwrite (overlay!)
            #pragma unroll
            for (int ni = 0; ni < 4; ++ni) {
                const int c2 = h * 32 + a_n0 / 2 + 4 * ni + tq;
                OS[(a_m0 + g)     * 68 + c2] = h2pack(oa[ni][0], oa[ni][1]);
                OS[(a_m0 + 8 + g) * 68 + c2] = h2pack(oa[ni][2], oa[ni][3]);
            }
            __syncthreads();
        }

        // =================== GEMM2: O1 = relu(O @ Ws0 + bs0) ===================
        {
            const u32* wssrc = WsT_g + (size_t)(e * 2 + 0) * 4 * 2560;
            const float* bsp = bs + (e * 2 + 0) * D_;
            float acc[4][4];
            #pragma unroll
            for (int ni = 0; ni < 4; ++ni) {
                const float b0v = bsp[g2_n0 + 8 * ni + 2 * tq];
                const float b1v = bsp[g2_n0 + 8 * ni + 2 * tq + 1];
                acc[ni][0] = b0v; acc[ni][1] = b1v; acc[ni][2] = b0v; acc[ni][3] = b1v;
            }
            #pragma unroll
            for (int j = tid; j < 640; j += 512)
                cp16(ws_smem + (u32)(j * 16), wssrc + j * 4);
            CP_COMMIT();
            for (int s = 0; s < 4; ++s) {
                const u32* cur = WS + (s & 1) * 5120;
                if (s < 3) {
                    const u32 boff = (u32)(((s + 1) & 1) * 5120 * 4);
                    const u32* src = wssrc + (s + 1) * 2560;
                    #pragma unroll
                    for (int j = tid; j < 640; j += 512)
                        cp16(ws_smem + boff + (u32)(j * 16), src + j * 4);
                    CP_COMMIT();
                    asm volatile("cp.async.wait_group 1;");
                } else {
                    asm volatile("cp.async.wait_group 0;");
                }
                __syncthreads();
                #pragma unroll
                for (int kk = 0; kk < 2; ++kk) {
                    const int d2g = s * 16 + kk * 8;
                    u32 a[4];
                    a[0] = OS[(g2_m0 + g)     * 68 + d2g + tq];
                    a[1] = OS[(g2_m0 + 8 + g) * 68 + d2g + tq];
                    a[2] = OS[(g2_m0 + g)     * 68 + d2g + tq + 4];
                    a[3] = OS[(g2_m0 + 8 + g) * 68 + d2g + tq + 4];
                    #pragma unroll
                    for (int ni = 0; ni < 4; ++ni) {
                        u32 bf[2];
                        bf[0] = cur[(g2_n0 + 8 * ni + g) * 20 + kk * 8 + tq];
                        bf[1] = cur[(g2_n0 + 8 * ni + g) * 20 + kk * 8 + tq + 4];
                        mma_f16(acc[ni], a, bf);
                    }
                }
                __syncthreads();
            }
            #pragma unroll
            for (int ni = 0; ni < 4; ++ni) {
                const int c2 = g2_n0 / 2 + 4 * ni + tq;
                O1[(g2_m0 + g)     * 68 + c2] = h2pack(fmaxf(acc[ni][0], 0.f), fmaxf(acc[ni][1], 0.f));
                O1[(g2_m0 + 8 + g) * 68 + c2] = h2pack(fmaxf(acc[ni][2], 0.f), fmaxf(acc[ni][3], 0.f));
            }
        }

        // =================== GEMM3: out_e = O1 @ Ws1 + bs1 ; accv += g*exp ===================
        {
            const u32* wssrc = WsT_g + (size_t)(e * 2 + 1) * 4 * 2560;
            const float* bsp = bs + (e * 2 + 1) * D_;
            float acc[4][4];
            #pragma unroll
            for (int ni = 0; ni < 4; ++ni) {
                const float b0v = bsp[g2_n0 + 8 * ni + 2 * tq];
                const float b1v = bsp[g2_n0 + 8 * ni + 2 * tq + 1];
                acc[ni][0] = b0v; acc[ni][1] = b1v; acc[ni][2] = b0v; acc[ni][3] = b1v;
            }
            #pragma unroll
            for (int j = tid; j < 640; j += 512)
                cp16(ws_smem + (u32)(j * 16), wssrc + j * 4);
            CP_COMMIT();
            __syncthreads();   // orders O1 stores before compute reads
            for (int s = 0; s < 4; ++s) {
                const u32* cur = WS + (s & 1) * 5120;
                if (s < 3) {
                    const u32 boff = (u32)(((s + 1) & 1) * 5120 * 4);
                    const u32* src = wssrc + (s + 1) * 2560;
                    #pragma unroll
                    for (int j = tid; j < 640; j += 512)
                        cp16(ws_smem + boff + (u32)(j * 16), src + j * 4);
                    CP_COMMIT();
                    asm volatile("cp.async.wait_group 1;");
                } else {
                    asm volatile("cp.async.wait_group 0;");
                }
                __syncthreads();
                #pragma unroll
                for (int kk = 0; kk < 2; ++kk) {
                    const int d2g = s * 16 + kk * 8;
                    u32 a[4];
                    a[0] = O1[(g2_m0 + g)     * 68 + d2g + tq];
                    a[1] = O1[(g2_m0 + 8 + g) * 68 + d2g + tq];
                    a[2] = O1[(g2_m0 + g)     * 68 + d2g + tq + 4];
                    a[3] = O1[(g2_m0 + 8 + g) * 68 + d2g + tq + 4];
                    #pragma unroll
                    for (int ni = 0; ni < 4; ++ni) {
                        u32 bf[2];
                        bf[0] = cur[(g2_n0 + 8 * ni + g) * 20 + kk * 8 + tq];
                        bf[1] = cur[(g2_n0 + 8 * ni + g) * 20 + kk * 8 + tq + 4];
                        mma_f16(acc[ni], a, bf);
                    }
                }
                __syncthreads();
            }
            #pragma unroll
            for (int ni = 0; ni < 4; ++ni)
                #pragma unroll
                for (int c = 0; c < 4; ++c)
                    accv[ni][c] += gg * __expf(acc[ni][c]);
        }
    }

    // ---- combine epilogue ----
    const float EPSF = 2.2204460492503131e-16f;
    #pragma unroll
    for (int ni = 0; ni < 4; ++ni) {
        const int cc  = g2_n0 + 8 * ni + 2 * tq;
        const int t0r = g2_m0 + g;
        const int t1r = g2_m0 + 8 + g;
        float v0 = accv[ni][0]; if (v0 == 0.f) v0 = EPSF;
        float v1 = accv[ni][1]; if (v1 == 0.f) v1 = EPSF;
        float v2 = accv[ni][2]; if (v2 == 0.f) v2 = EPSF;
        float v3 = accv[ni][3]; if (v3 == 0.f) v3 = EPSF;
        *(u64*)&out[(((size_t)b * T_ + t0r) * N_ + n) * D_ + cc] = fpack(__logf(v0), __logf(v1));
        *(u64*)&out[(((size_t)b * T_ + t1r) * N_ + n) * D_ + cc] = fpack(__logf(v2), __logf(v3));
    }
}

// ---------------------------------------------------------------------------
// launcher
// ---------------------------------------------------------------------------
extern "C" void kernel_launch(void* const* d_in, const int* in_sizes, int n_in,
                              void* d_out, int out_size) {
    const float* x  = (const float*)d_in[0];
    const float* Wg = (const float*)d_in[1];
    const float* Wd = (const float*)d_in[2];
    const float* bd = (const float*)d_in[3];
    const float* Ws = (const float*)d_in[4];
    const float* bs = (const float*)d_in[5];
    float* out = (float*)d_out;

    const int smem_bytes = SMEM_U * 4; // 147456 B
    cudaFuncSetAttribute(moe_kernel, cudaFuncAttributeMaxDynamicSharedMemorySize, smem_bytes);

    prep_kernel<<<2112, 256>>>(Wd, Ws);
    dim3 pgrid(32, B_);
    gate_partial<<<pgrid, 128>>>(x);
    gate_kernel<<<B_, 128>>>(Wg);
    dim3 grid(N_, B_);
    moe_kernel<<<grid, 512, smem_bytes>>>(x, bd, bs, out);
}